// round 5
// baseline (speedup 1.0000x reference)
#include <cuda_runtime.h>
#include <cuda_bf16.h>
#include <math.h>
#include <stdint.h>

#define NTOK 4096
#define SQ   1024
#define BATCH 4
#define HIDD 2048
#define NH   16
#define NKV  4
#define HDIM 128
#define QKVD 3072   // (16+2*4)*128
#define INTD 8192

// ---------------- scratch (static device memory; no allocations) ----------------
__device__ float g_xn  [(size_t)NTOK * HIDD];
__device__ float g_qkv [(size_t)NTOK * QKVD];
__device__ float g_attn[(size_t)NTOK * HIDD];
__device__ float g_h1  [(size_t)NTOK * HIDD];
__device__ float g_h2  [(size_t)NTOK * HIDD];
__device__ float g_gu  [(size_t)NTOK * 2 * INTD];
__device__ float g_act [(size_t)NTOK * INTD];
// transposed + tf32-rounded weights [N, K] K-major
__device__ float g_wqkvT [(size_t)QKVD * HIDD];
__device__ float g_woT   [(size_t)HIDD * HIDD];
__device__ float g_wguT  [(size_t)2 * INTD * HIDD];
__device__ float g_wdnT  [(size_t)HIDD * INTD];

// ---------------- helpers ----------------
__device__ __forceinline__ float tf32rnd(float x) {
    uint32_t u;
    asm("cvt.rna.tf32.f32 %0, %1;" : "=r"(u) : "f"(x));
    return __uint_as_float(u);
}

__device__ __forceinline__ uint32_t smem_u32(const void* p) {
    uint32_t a;
    asm("{ .reg .u64 t; cvta.to.shared.u64 t, %1; cvt.u32.u64 %0, t; }"
        : "=r"(a) : "l"(p));
    return a;
}

__device__ __forceinline__ uint32_t lds_u32(uint32_t a) {
    uint32_t v;
    asm volatile("ld.shared.b32 %0, [%1];" : "=r"(v) : "r"(a));
    return v;
}

#define SWZ128(o) ((o) ^ (((o) >> 3) & 0x70))

#define CP_ASYNC16(dst, src) \
    asm volatile("cp.async.cg.shared.global [%0], [%1], 16;" :: "r"(dst), "l"(src) : "memory")
#define CP_COMMIT() asm volatile("cp.async.commit_group;" ::: "memory")

__device__ __forceinline__ void mma_tf32(float* c, const uint32_t* a, const uint32_t* b) {
    asm volatile(
        "mma.sync.aligned.m16n8k8.row.col.f32.tf32.tf32.f32 "
        "{%0,%1,%2,%3}, {%4,%5,%6,%7}, {%8,%9}, {%0,%1,%2,%3};\n"
        : "+f"(c[0]), "+f"(c[1]), "+f"(c[2]), "+f"(c[3])
        : "r"(a[0]), "r"(a[1]), "r"(a[2]), "r"(a[3]), "r"(b[0]), "r"(b[1]));
}

// ---------------- HMMA tf32 GEMM: tile 256(M) x 128(N), kc=32, 3-stage cp.async --------
#define TM 256
#define TN 128
#define KC 32
#define NSTG 3
#define ASZ (TM * KC * 4)
#define BSZ (TN * KC * 4)
#define STGB (ASZ + BSZ)
#define GEMM_SMEM_TC (NSTG * STGB)

template <bool RES>
__global__ __launch_bounds__(256, 1) void tc_gemm(const float* __restrict__ A,
                                                  const float* __restrict__ Bt,
                                                  const float* __restrict__ R,
                                                  float* __restrict__ C,
                                                  int N, int K) {
    extern __shared__ char smc[];
    const uint32_t sb = smem_u32(smc);
    const int tid = threadIdx.x;
    const int lane = tid & 31, w = tid >> 5;
    const int wm = w >> 1, wn = w & 1;
    const int g = lane >> 2, tg = lane & 3;
    const int by = blockIdx.x, bx = blockIdx.y;

    const float* Ab = A + (size_t)(by * TM) * K;
    const float* Bb = Bt + (size_t)(bx * TN) * K;
    const int nk = K / KC;

    const int lrow = tid >> 3;
    const int lseg = tid & 7;

    float acc[4][8][4];
#pragma unroll
    for (int i = 0; i < 4; i++)
#pragma unroll
        for (int j = 0; j < 8; j++)
#pragma unroll
            for (int z = 0; z < 4; z++) acc[i][j][z] = 0.f;

    auto load_chunk = [&](int j) {
        uint32_t st = sb + (j % NSTG) * STGB;
#pragma unroll
        for (int i = 0; i < 8; i++) {
            int r = i * 32 + lrow;
            uint32_t off = (uint32_t)(r * 128 + lseg * 16);
            CP_ASYNC16(st + SWZ128(off), Ab + (size_t)r * K + j * KC + lseg * 4);
        }
        uint32_t stB = st + ASZ;
#pragma unroll
        for (int i = 0; i < 4; i++) {
            int r = i * 32 + lrow;
            uint32_t off = (uint32_t)(r * 128 + lseg * 16);
            CP_ASYNC16(stB + SWZ128(off), Bb + (size_t)r * K + j * KC + lseg * 4);
        }
        CP_COMMIT();
    };

    for (int j = 0; j < NSTG - 1 && j < nk; j++) load_chunk(j);

    for (int it = 0; it < nk; it++) {
        if (it < nk - 1)
            asm volatile("cp.async.wait_group 1;" ::: "memory");
        else
            asm volatile("cp.async.wait_group 0;" ::: "memory");
        __syncthreads();
        if (it + NSTG - 1 < nk) load_chunk(it + NSTG - 1);

        const uint32_t sA = sb + (it % NSTG) * STGB;
        const uint32_t sB = sA + ASZ;
#pragma unroll
        for (int kk = 0; kk < 4; kk++) {
            const int k0 = kk * 8;
            uint32_t af[4][4];
#pragma unroll
            for (int mf = 0; mf < 4; mf++) {
                int r0 = wm * 64 + mf * 16 + g;
                uint32_t ro = sA + r0 * 128;
                uint32_t kx = (uint32_t)((r0 & 7) << 4);
                uint32_t kl = ((uint32_t)((k0 + tg) * 4)) ^ kx;
                uint32_t kh = ((uint32_t)((k0 + tg + 4) * 4)) ^ kx;
                af[mf][0] = lds_u32(ro + kl);
                af[mf][1] = lds_u32(ro + 1024 + kl);
                af[mf][2] = lds_u32(ro + kh);
                af[mf][3] = lds_u32(ro + 1024 + kh);
            }
            uint32_t bf[8][2];
#pragma unroll
            for (int nf = 0; nf < 8; nf++) {
                int r = wn * 64 + nf * 8 + g;
                uint32_t ro = sB + r * 128;
                uint32_t kx = (uint32_t)((r & 7) << 4);
                bf[nf][0] = lds_u32(ro + (((uint32_t)((k0 + tg) * 4)) ^ kx));
                bf[nf][1] = lds_u32(ro + (((uint32_t)((k0 + tg + 4) * 4)) ^ kx));
            }
#pragma unroll
            for (int mf = 0; mf < 4; mf++)
#pragma unroll
                for (int nf = 0; nf < 8; nf++)
                    mma_tf32(acc[mf][nf], af[mf], bf[nf]);
        }
        __syncthreads();
    }

#pragma unroll
    for (int mf = 0; mf < 4; mf++) {
#pragma unroll
        for (int half = 0; half < 2; half++) {
            int row = by * TM + wm * 64 + mf * 16 + g + half * 8;
            float* Crow = C + (size_t)row * N + bx * TN + wn * 64;
            const float* Rrow = RES ? (R + (size_t)row * N + bx * TN + wn * 64)
                                    : (const float*)0;
#pragma unroll
            for (int nf = 0; nf < 8; nf++) {
                int col = nf * 8 + tg * 2;
                float2 v = make_float2(acc[mf][nf][half * 2 + 0],
                                       acc[mf][nf][half * 2 + 1]);
                if (RES) {
                    v.x += Rrow[col];
                    v.y += Rrow[col + 1];
                }
                *(float2*)(Crow + col) = v;
            }
        }
    }
}

// ---------------- weight transpose + tf32 round ----------------
__global__ void transpose_round_kernel(const float* __restrict__ in,
                                       float* __restrict__ out, int K, int N) {
    __shared__ float t[32][33];
    int n0 = blockIdx.x * 32, k0 = blockIdx.y * 32;
    int tx = threadIdx.x, ty = threadIdx.y;
#pragma unroll
    for (int r = 0; r < 4; r++)
        t[ty + r * 8][tx] = in[(size_t)(k0 + ty + r * 8) * N + n0 + tx];
    __syncthreads();
#pragma unroll
    for (int r = 0; r < 4; r++)
        out[(size_t)(n0 + ty + r * 8) * K + k0 + tx] = tf32rnd(t[tx][ty + r * 8]);
}

// ---------------- RMSNorm (output tf32-rounded) ----------------
__global__ void rmsnorm_kernel(const float* __restrict__ x, const float* __restrict__ w,
                               float* __restrict__ out) {
    int row = blockIdx.x;
    const float* xr = x + (size_t)row * HIDD;
    __shared__ float red[256];
    float4 vals[2];
    float s = 0.f;
#pragma unroll
    for (int i = 0; i < 2; i++) {
        float4 v = *(const float4*)(xr + (threadIdx.x + i * 256) * 4);
        vals[i] = v;
        s += v.x * v.x + v.y * v.y + v.z * v.z + v.w * v.w;
    }
    red[threadIdx.x] = s;
    __syncthreads();
    for (int off = 128; off > 0; off >>= 1) {
        if (threadIdx.x < off) red[threadIdx.x] += red[threadIdx.x + off];
        __syncthreads();
    }
    float inv = rsqrtf(red[0] / (float)HIDD + 1e-6f);
#pragma unroll
    for (int i = 0; i < 2; i++) {
        int c = (threadIdx.x + i * 256) * 4;
        float4 v = vals[i];
        float4 wv = *(const float4*)(w + c);
        float4 o = make_float4(tf32rnd(v.x * inv * wv.x), tf32rnd(v.y * inv * wv.y),
                               tf32rnd(v.z * inv * wv.z), tf32rnd(v.w * inv * wv.w));
        *(float4*)(out + (size_t)row * HIDD + c) = o;
    }
}

// ---------------- RoPE ----------------
__global__ void rope_kernel(float* __restrict__ qkv, const int* __restrict__ pos) {
    __shared__ float cs[64], sn[64];
    int tok = blockIdx.x;
    int p = pos[tok % SQ];
    if (threadIdx.x < 64) {
        double freq = exp(-(double)threadIdx.x * (9.210340371976184 / 64.0));
        float ang = (float)((double)p * freq);
        float s, c;
        sincosf(ang, &s, &c);
        cs[threadIdx.x] = c;
        sn[threadIdx.x] = s;
    }
    __syncthreads();
    for (int item = threadIdx.x; item < (NH + NKV) * 64; item += blockDim.x) {
        int head = item >> 6;
        int d = item & 63;
        float c = cs[d], s = sn[d];
        float* base = qkv + (size_t)tok * QKVD + head * HDIM;
        float t1 = base[d];
        float t2 = base[d + 64];
        base[d]      = t1 * c - t2 * s;
        base[d + 64] = t2 * c + t1 * s;
    }
}

// ---------------- Tensor-core flash attention (tf32 mma, causal, GQA) ----------------
// grid (SQ/128, NH, BATCH), 256 threads (8 warps x 16 q-rows).
// smem pitches: Q/K = 132 words (bank = 4g+tg), V = 136 (bank = 8tg+g), P = 68.
#define QP 132
#define VP 136
#define PP 68
#define ATTN_SMEM ((128 * QP + 64 * QP + 64 * VP + 128 * PP) * 4)

__global__ __launch_bounds__(256, 1) void attn_mma_kernel(const float* __restrict__ qkv,
                                                          float* __restrict__ attn_out) {
    extern __shared__ float smem[];
    float* Qs = smem;                    // 128 x QP
    float* Ks = Qs + 128 * QP;           // 64 x QP
    float* Vs = Ks + 64 * QP;            // 64 x VP
    float* Ps = Vs + 64 * VP;            // 128 x PP

    const int qt = (gridDim.x - 1) - blockIdx.x;  // heavy tiles first (LPT)
    const int h = blockIdx.y, b = blockIdx.z;
    const int kvh = h / (NH / NKV);
    const int tid = threadIdx.x, w = tid >> 5, lane = tid & 31;
    const int g = lane >> 2, tg = lane & 3;
    const int tokQ0 = b * SQ + qt * 128;

    const uint32_t sQ = smem_u32(Qs), sK = smem_u32(Ks), sV = smem_u32(Vs),
                   sP = smem_u32(Ps);

    // load + round Q tile (128 x 128)
    for (int i = tid; i < 128 * 32; i += 256) {
        int r = i >> 5, c4 = (i & 31) * 4;
        float4 v = *(const float4*)(qkv + (size_t)(tokQ0 + r) * QKVD + h * HDIM + c4);
        v.x = tf32rnd(v.x); v.y = tf32rnd(v.y); v.z = tf32rnd(v.z); v.w = tf32rnd(v.w);
        *(float4*)(Qs + r * QP + c4) = v;
    }

    float o[16][4];
#pragma unroll
    for (int nf = 0; nf < 16; nf++)
#pragma unroll
        for (int z = 0; z < 4; z++) o[nf][z] = 0.f;
    float m0 = -1e30f, m1 = -1e30f, l0 = 0.f, l1 = 0.f;
    const float scale = 0.08838834764831845f;

    const int row0 = qt * 128 + w * 16 + g;   // thread's first global q row
    const int ntile = 2 * qt + 2;

    for (int kt = 0; kt < ntile; kt++) {
        __syncthreads();
        {
            int tokK0 = b * SQ + kt * 64;
            for (int i = tid; i < 64 * 32; i += 256) {
                int r = i >> 5, c4 = (i & 31) * 4;
                const float* base = qkv + (size_t)(tokK0 + r) * QKVD;
                float4 kv = *(const float4*)(base + NH * HDIM + kvh * HDIM + c4);
                kv.x = tf32rnd(kv.x); kv.y = tf32rnd(kv.y);
                kv.z = tf32rnd(kv.z); kv.w = tf32rnd(kv.w);
                *(float4*)(Ks + r * QP + c4) = kv;
                float4 vv = *(const float4*)(base + (NH + NKV) * HDIM + kvh * HDIM + c4);
                vv.x = tf32rnd(vv.x); vv.y = tf32rnd(vv.y);
                vv.z = tf32rnd(vv.z); vv.w = tf32rnd(vv.w);
                *(float4*)(Vs + r * VP + c4) = vv;
            }
        }
        __syncthreads();

        // warp active if any of its rows can attend to this tile
        if (kt * 64 > qt * 128 + w * 16 + 15) continue;

        // ---- S = Q @ K^T  (16 x 64, k=128) ----
        float s[8][4];
#pragma unroll
        for (int nf = 0; nf < 8; nf++)
#pragma unroll
            for (int z = 0; z < 4; z++) s[nf][z] = 0.f;

        const uint32_t qrow = sQ + (uint32_t)((w * 16 + g) * QP) * 4;
#pragma unroll 4
        for (int ks = 0; ks < 16; ks++) {
            uint32_t a[4];
            uint32_t ko = (uint32_t)(ks * 8 + tg) * 4;
            a[0] = lds_u32(qrow + ko);
            a[1] = lds_u32(qrow + (uint32_t)(8 * QP) * 4 + ko);
            a[2] = lds_u32(qrow + ko + 16);
            a[3] = lds_u32(qrow + (uint32_t)(8 * QP) * 4 + ko + 16);
#pragma unroll
            for (int nf = 0; nf < 8; nf++) {
                uint32_t krow = sK + (uint32_t)((nf * 8 + g) * QP) * 4;
                uint32_t bfr[2];
                bfr[0] = lds_u32(krow + ko);
                bfr[1] = lds_u32(krow + ko + 16);
                mma_tf32(s[nf], a, bfr);
            }
        }

        // ---- online softmax ----
        const bool domask = (kt >= 2 * qt);
        float mx0 = -1e30f, mx1 = -1e30f;
#pragma unroll
        for (int nf = 0; nf < 8; nf++) {
#pragma unroll
            for (int z = 0; z < 4; z++) {
                float v = s[nf][z] * scale;
                if (domask) {
                    int col = kt * 64 + nf * 8 + 2 * tg + (z & 1);
                    int row = (z < 2) ? row0 : row0 + 8;
                    if (col > row) v = -1e30f;
                }
                s[nf][z] = v;
            }
            mx0 = fmaxf(mx0, fmaxf(s[nf][0], s[nf][1]));
            mx1 = fmaxf(mx1, fmaxf(s[nf][2], s[nf][3]));
        }
        mx0 = fmaxf(mx0, __shfl_xor_sync(0xffffffffu, mx0, 1));
        mx0 = fmaxf(mx0, __shfl_xor_sync(0xffffffffu, mx0, 2));
        mx1 = fmaxf(mx1, __shfl_xor_sync(0xffffffffu, mx1, 1));
        mx1 = fmaxf(mx1, __shfl_xor_sync(0xffffffffu, mx1, 2));
        float mn0 = fmaxf(m0, mx0), mn1 = fmaxf(m1, mx1);
        float c0 = __expf(m0 - mn0), c1 = __expf(m1 - mn1);
        float sum0 = 0.f, sum1 = 0.f;
        float* prow0 = Ps + (w * 16 + g) * PP + 2 * tg;
        float* prow1 = prow0 + 8 * PP;
#pragma unroll
        for (int nf = 0; nf < 8; nf++) {
            float p0 = tf32rnd(__expf(s[nf][0] - mn0));
            float p1 = tf32rnd(__expf(s[nf][1] - mn0));
            float p2 = tf32rnd(__expf(s[nf][2] - mn1));
            float p3 = tf32rnd(__expf(s[nf][3] - mn1));
            sum0 += p0 + p1;
            sum1 += p2 + p3;
            *(float2*)(prow0 + nf * 8) = make_float2(p0, p1);
            *(float2*)(prow1 + nf * 8) = make_float2(p2, p3);
        }
        sum0 += __shfl_xor_sync(0xffffffffu, sum0, 1);
        sum0 += __shfl_xor_sync(0xffffffffu, sum0, 2);
        sum1 += __shfl_xor_sync(0xffffffffu, sum1, 1);
        sum1 += __shfl_xor_sync(0xffffffffu, sum1, 2);
        l0 = l0 * c0 + sum0;
        l1 = l1 * c1 + sum1;
        m0 = mn0; m1 = mn1;
#pragma unroll
        for (int nf = 0; nf < 16; nf++) {
            o[nf][0] *= c0; o[nf][1] *= c0;
            o[nf][2] *= c1; o[nf][3] *= c1;
        }
        __syncwarp();

        // ---- O += P @ V  (16 x 128, k=64) ----
        const uint32_t prow = sP + (uint32_t)((w * 16 + g) * PP) * 4;
#pragma unroll
        for (int ks = 0; ks < 8; ks++) {
            uint32_t a[4];
            uint32_t ko = (uint32_t)(ks * 8 + tg) * 4;
            a[0] = lds_u32(prow + ko);
            a[1] = lds_u32(prow + (uint32_t)(8 * PP) * 4 + ko);
            a[2] = lds_u32(prow + ko + 16);
            a[3] = lds_u32(prow + (uint32_t)(8 * PP) * 4 + ko + 16);
            uint32_t v0 = sV + (uint32_t)((ks * 8 + tg) * VP + g) * 4;
            uint32_t v1 = sV + (uint32_t)((ks * 8 + tg + 4) * VP + g) * 4;
#pragma unroll
            for (int nf = 0; nf < 16; nf++) {
                uint32_t bfr[2];
                bfr[0] = lds_u32(v0 + nf * 32);
                bfr[1] = lds_u32(v1 + nf * 32);
                mma_tf32(o[nf], a, bfr);
            }
        }
    }

    // ---- epilogue ----
    float inv0 = 1.f / l0, inv1 = 1.f / l1;
    float* orow0 = attn_out + (size_t)(tokQ0 + w * 16 + g) * HIDD + h * HDIM;
    float* orow1 = orow0 + (size_t)8 * HIDD;
#pragma unroll
    for (int nf = 0; nf < 16; nf++) {
        int col = nf * 8 + 2 * tg;
        *(float2*)(orow0 + col) = make_float2(tf32rnd(o[nf][0] * inv0),
                                              tf32rnd(o[nf][1] * inv0));
        *(float2*)(orow1 + col) = make_float2(tf32rnd(o[nf][2] * inv1),
                                              tf32rnd(o[nf][3] * inv1));
    }
}

// ---------------- SiLU(gate) * up (output tf32-rounded) ----------------
__global__ void silu_kernel(const float* __restrict__ gu, float* __restrict__ act) {
    size_t n4 = (size_t)NTOK * INTD / 4;
    for (size_t idx = (size_t)blockIdx.x * blockDim.x + threadIdx.x; idx < n4;
         idx += (size_t)gridDim.x * blockDim.x) {
        size_t t = idx / (INTD / 4);
        size_t c = (idx % (INTD / 4)) * 4;
        float4 g = *(const float4*)(gu + t * (2 * INTD) + c);
        float4 u = *(const float4*)(gu + t * (2 * INTD) + INTD + c);
        float4 o;
        o.x = tf32rnd(g.x / (1.f + __expf(-g.x)) * u.x);
        o.y = tf32rnd(g.y / (1.f + __expf(-g.y)) * u.y);
        o.z = tf32rnd(g.z / (1.f + __expf(-g.z)) * u.z);
        o.w = tf32rnd(g.w / (1.f + __expf(-g.w)) * u.w);
        *(float4*)(act + idx * 4) = o;
    }
}

extern "C" void kernel_launch(void* const* d_in, const int* in_sizes, int n_in,
                              void* d_out, int out_size) {
    const float* x    = (const float*)d_in[0];
    const float* ln1  = (const float*)d_in[1];
    const float* wqkv = (const float*)d_in[2];
    const float* wo   = (const float*)d_in[3];
    const float* ln2  = (const float*)d_in[4];
    const float* wgu  = (const float*)d_in[5];
    const float* wdn  = (const float*)d_in[6];
    const int*   pos  = (const int*)d_in[7];
    float* out = (float*)d_out;

    void *xn, *qkv, *attn, *h1, *h2, *gu, *act;
    void *wqkvT, *woT, *wguT, *wdnT;
    cudaGetSymbolAddress(&xn, g_xn);
    cudaGetSymbolAddress(&qkv, g_qkv);
    cudaGetSymbolAddress(&attn, g_attn);
    cudaGetSymbolAddress(&h1, g_h1);
    cudaGetSymbolAddress(&h2, g_h2);
    cudaGetSymbolAddress(&gu, g_gu);
    cudaGetSymbolAddress(&act, g_act);
    cudaGetSymbolAddress(&wqkvT, g_wqkvT);
    cudaGetSymbolAddress(&woT, g_woT);
    cudaGetSymbolAddress(&wguT, g_wguT);
    cudaGetSymbolAddress(&wdnT, g_wdnT);

    cudaFuncSetAttribute(attn_mma_kernel, cudaFuncAttributeMaxDynamicSharedMemorySize, ATTN_SMEM);
    cudaFuncSetAttribute(tc_gemm<false>, cudaFuncAttributeMaxDynamicSharedMemorySize, GEMM_SMEM_TC);
    cudaFuncSetAttribute(tc_gemm<true>,  cudaFuncAttributeMaxDynamicSharedMemorySize, GEMM_SMEM_TC);

    // 0. weight transpose + tf32 rounding
    {
        dim3 bb(32, 8);
        transpose_round_kernel<<<dim3(QKVD / 32, HIDD / 32), bb>>>(wqkv, (float*)wqkvT, HIDD, QKVD);
        transpose_round_kernel<<<dim3(HIDD / 32, HIDD / 32), bb>>>(wo, (float*)woT, HIDD, HIDD);
        transpose_round_kernel<<<dim3(2 * INTD / 32, HIDD / 32), bb>>>(wgu, (float*)wguT, HIDD, 2 * INTD);
        transpose_round_kernel<<<dim3(HIDD / 32, INTD / 32), bb>>>(wdn, (float*)wdnT, INTD, HIDD);
    }
    // 1. h = rmsnorm(x, ln1)
    rmsnorm_kernel<<<NTOK, 256>>>(x, ln1, (float*)xn);
    // 2. qkv = h @ wqkv
    tc_gemm<false><<<dim3(NTOK / TM, QKVD / TN), 256, GEMM_SMEM_TC>>>(
        (const float*)xn, (const float*)wqkvT, nullptr, (float*)qkv, QKVD, HIDD);
    // 3. RoPE
    rope_kernel<<<NTOK, 256>>>((float*)qkv, pos);
    // 4. attention (tensor-core)
    {
        dim3 g(SQ / 128, NH, BATCH);
        attn_mma_kernel<<<g, 256, ATTN_SMEM>>>((const float*)qkv, (float*)attn);
    }
    // 5. h1 = x + attn @ wo
    tc_gemm<true><<<dim3(NTOK / TM, HIDD / TN), 256, GEMM_SMEM_TC>>>(
        (const float*)attn, (const float*)woT, x, (float*)h1, HIDD, HIDD);
    // 6. h2 = rmsnorm(h1, ln2)
    rmsnorm_kernel<<<NTOK, 256>>>((const float*)h1, ln2, (float*)h2);
    // 7. gu = h2 @ w_gate_up
    tc_gemm<false><<<dim3(NTOK / TM, 2 * INTD / TN), 256, GEMM_SMEM_TC>>>(
        (const float*)h2, (const float*)wguT, nullptr, (float*)gu, 2 * INTD, HIDD);
    // 8. act = silu(gate)*up
    silu_kernel<<<2048, 256>>>((const float*)gu, (float*)act);
    // 9. out = h1 + act @ w_down
    tc_gemm<true><<<dim3(NTOK / TM, HIDD / TN), 256, GEMM_SMEM_TC>>>(
        (const float*)act, (const float*)wdnT, (const float*)h1, out, HIDD, INTD);
}

// round 6
// speedup vs baseline: 1.5273x; 1.5273x over previous
#include <cuda_runtime.h>
#include <cuda_bf16.h>
#include <math.h>
#include <stdint.h>

#define NTOK 4096
#define SQ   1024
#define BATCH 4
#define HIDD 2048
#define NH   16
#define NKV  4
#define HDIM 128
#define QKVD 3072   // (16+2*4)*128
#define INTD 8192

// ---------------- scratch (static device memory; no allocations) ----------------
__device__ float g_xn  [(size_t)NTOK * HIDD];
__device__ float g_qkv [(size_t)NTOK * QKVD];
__device__ float g_attn[(size_t)NTOK * HIDD];
__device__ float g_h1  [(size_t)NTOK * HIDD];
__device__ float g_h2  [(size_t)NTOK * HIDD];
__device__ float g_gu  [(size_t)NTOK * 2 * INTD];
__device__ float g_act [(size_t)NTOK * INTD];
// transposed + tf32-rounded weights [N, K] K-major
__device__ float g_wqkvT [(size_t)QKVD * HIDD];
__device__ float g_woT   [(size_t)HIDD * HIDD];
__device__ float g_wguT  [(size_t)2 * INTD * HIDD];
__device__ float g_wdnT  [(size_t)HIDD * INTD];

// ---------------- helpers ----------------
__device__ __forceinline__ float tf32rnd(float x) {
    uint32_t u;
    asm("cvt.rna.tf32.f32 %0, %1;" : "=r"(u) : "f"(x));
    return __uint_as_float(u);
}

__device__ __forceinline__ uint32_t smem_u32(const void* p) {
    uint32_t a;
    asm("{ .reg .u64 t; cvta.to.shared.u64 t, %1; cvt.u32.u64 %0, t; }"
        : "=r"(a) : "l"(p));
    return a;
}

__device__ __forceinline__ uint32_t lds_u32(uint32_t a) {
    uint32_t v;
    asm volatile("ld.shared.b32 %0, [%1];" : "=r"(v) : "r"(a));
    return v;
}

#define SWZ128(o) ((o) ^ (((o) >> 3) & 0x70))

#define CP_ASYNC16(dst, src) \
    asm volatile("cp.async.cg.shared.global [%0], [%1], 16;" :: "r"(dst), "l"(src) : "memory")
#define CP_COMMIT() asm volatile("cp.async.commit_group;" ::: "memory")

__device__ __forceinline__ void mma_tf32(float* c, const uint32_t* a, const uint32_t* b) {
    asm volatile(
        "mma.sync.aligned.m16n8k8.row.col.f32.tf32.tf32.f32 "
        "{%0,%1,%2,%3}, {%4,%5,%6,%7}, {%8,%9}, {%0,%1,%2,%3};\n"
        : "+f"(c[0]), "+f"(c[1]), "+f"(c[2]), "+f"(c[3])
        : "r"(a[0]), "r"(a[1]), "r"(a[2]), "r"(a[3]), "r"(b[0]), "r"(b[1]));
}

// ---------------- HMMA tf32 GEMM: tile 256(M) x 128(N), kc=32, 3-stage cp.async --------
#define TM 256
#define TN 128
#define KC 32
#define NSTG 3
#define ASZ (TM * KC * 4)
#define BSZ (TN * KC * 4)
#define STGB (ASZ + BSZ)
#define GEMM_SMEM_TC (NSTG * STGB)

template <bool RES>
__global__ __launch_bounds__(256, 1) void tc_gemm(const float* __restrict__ A,
                                                  const float* __restrict__ Bt,
                                                  const float* __restrict__ R,
                                                  float* __restrict__ C,
                                                  int N, int K) {
    extern __shared__ char smc[];
    const uint32_t sb = smem_u32(smc);
    const int tid = threadIdx.x;
    const int lane = tid & 31, w = tid >> 5;
    const int wm = w >> 1, wn = w & 1;
    const int g = lane >> 2, tg = lane & 3;
    const int by = blockIdx.x, bx = blockIdx.y;

    const float* Ab = A + (size_t)(by * TM) * K;
    const float* Bb = Bt + (size_t)(bx * TN) * K;
    const int nk = K / KC;

    const int lrow = tid >> 3;
    const int lseg = tid & 7;

    float acc[4][8][4];
#pragma unroll
    for (int i = 0; i < 4; i++)
#pragma unroll
        for (int j = 0; j < 8; j++)
#pragma unroll
            for (int z = 0; z < 4; z++) acc[i][j][z] = 0.f;

    auto load_chunk = [&](int j) {
        uint32_t st = sb + (j % NSTG) * STGB;
#pragma unroll
        for (int i = 0; i < 8; i++) {
            int r = i * 32 + lrow;
            uint32_t off = (uint32_t)(r * 128 + lseg * 16);
            CP_ASYNC16(st + SWZ128(off), Ab + (size_t)r * K + j * KC + lseg * 4);
        }
        uint32_t stB = st + ASZ;
#pragma unroll
        for (int i = 0; i < 4; i++) {
            int r = i * 32 + lrow;
            uint32_t off = (uint32_t)(r * 128 + lseg * 16);
            CP_ASYNC16(stB + SWZ128(off), Bb + (size_t)r * K + j * KC + lseg * 4);
        }
        CP_COMMIT();
    };

    for (int j = 0; j < NSTG - 1 && j < nk; j++) load_chunk(j);

    for (int it = 0; it < nk; it++) {
        if (it < nk - 1)
            asm volatile("cp.async.wait_group 1;" ::: "memory");
        else
            asm volatile("cp.async.wait_group 0;" ::: "memory");
        __syncthreads();
        if (it + NSTG - 1 < nk) load_chunk(it + NSTG - 1);

        const uint32_t sA = sb + (it % NSTG) * STGB;
        const uint32_t sB = sA + ASZ;
#pragma unroll
        for (int kk = 0; kk < 4; kk++) {
            const int k0 = kk * 8;
            uint32_t af[4][4];
#pragma unroll
            for (int mf = 0; mf < 4; mf++) {
                int r0 = wm * 64 + mf * 16 + g;
                uint32_t ro = sA + r0 * 128;
                uint32_t kx = (uint32_t)((r0 & 7) << 4);
                uint32_t kl = ((uint32_t)((k0 + tg) * 4)) ^ kx;
                uint32_t kh = ((uint32_t)((k0 + tg + 4) * 4)) ^ kx;
                af[mf][0] = lds_u32(ro + kl);
                af[mf][1] = lds_u32(ro + 1024 + kl);
                af[mf][2] = lds_u32(ro + kh);
                af[mf][3] = lds_u32(ro + 1024 + kh);
            }
            uint32_t bf[8][2];
#pragma unroll
            for (int nf = 0; nf < 8; nf++) {
                int r = wn * 64 + nf * 8 + g;
                uint32_t ro = sB + r * 128;
                uint32_t kx = (uint32_t)((r & 7) << 4);
                bf[nf][0] = lds_u32(ro + (((uint32_t)((k0 + tg) * 4)) ^ kx));
                bf[nf][1] = lds_u32(ro + (((uint32_t)((k0 + tg + 4) * 4)) ^ kx));
            }
#pragma unroll
            for (int mf = 0; mf < 4; mf++)
#pragma unroll
                for (int nf = 0; nf < 8; nf++)
                    mma_tf32(acc[mf][nf], af[mf], bf[nf]);
        }
        __syncthreads();
    }

#pragma unroll
    for (int mf = 0; mf < 4; mf++) {
#pragma unroll
        for (int half = 0; half < 2; half++) {
            int row = by * TM + wm * 64 + mf * 16 + g + half * 8;
            float* Crow = C + (size_t)row * N + bx * TN + wn * 64;
            const float* Rrow = RES ? (R + (size_t)row * N + bx * TN + wn * 64)
                                    : (const float*)0;
#pragma unroll
            for (int nf = 0; nf < 8; nf++) {
                int col = nf * 8 + tg * 2;
                float2 v = make_float2(acc[mf][nf][half * 2 + 0],
                                       acc[mf][nf][half * 2 + 1]);
                if (RES) {
                    v.x += Rrow[col];
                    v.y += Rrow[col + 1];
                }
                *(float2*)(Crow + col) = v;
            }
        }
    }
}

// ---------------- weight transpose + tf32 round ----------------
__global__ void transpose_round_kernel(const float* __restrict__ in,
                                       float* __restrict__ out, int K, int N) {
    __shared__ float t[32][33];
    int n0 = blockIdx.x * 32, k0 = blockIdx.y * 32;
    int tx = threadIdx.x, ty = threadIdx.y;
#pragma unroll
    for (int r = 0; r < 4; r++)
        t[ty + r * 8][tx] = in[(size_t)(k0 + ty + r * 8) * N + n0 + tx];
    __syncthreads();
#pragma unroll
    for (int r = 0; r < 4; r++)
        out[(size_t)(n0 + ty + r * 8) * K + k0 + tx] = tf32rnd(t[tx][ty + r * 8]);
}

// ---------------- RMSNorm (output tf32-rounded) ----------------
__global__ void rmsnorm_kernel(const float* __restrict__ x, const float* __restrict__ w,
                               float* __restrict__ out) {
    int row = blockIdx.x;
    const float* xr = x + (size_t)row * HIDD;
    __shared__ float red[256];
    float4 vals[2];
    float s = 0.f;
#pragma unroll
    for (int i = 0; i < 2; i++) {
        float4 v = *(const float4*)(xr + (threadIdx.x + i * 256) * 4);
        vals[i] = v;
        s += v.x * v.x + v.y * v.y + v.z * v.z + v.w * v.w;
    }
    red[threadIdx.x] = s;
    __syncthreads();
    for (int off = 128; off > 0; off >>= 1) {
        if (threadIdx.x < off) red[threadIdx.x] += red[threadIdx.x + off];
        __syncthreads();
    }
    float inv = rsqrtf(red[0] / (float)HIDD + 1e-6f);
#pragma unroll
    for (int i = 0; i < 2; i++) {
        int c = (threadIdx.x + i * 256) * 4;
        float4 v = vals[i];
        float4 wv = *(const float4*)(w + c);
        float4 o = make_float4(tf32rnd(v.x * inv * wv.x), tf32rnd(v.y * inv * wv.y),
                               tf32rnd(v.z * inv * wv.z), tf32rnd(v.w * inv * wv.w));
        *(float4*)(out + (size_t)row * HIDD + c) = o;
    }
}

// ---------------- RoPE ----------------
__global__ void rope_kernel(float* __restrict__ qkv, const int* __restrict__ pos) {
    __shared__ float cs[64], sn[64];
    int tok = blockIdx.x;
    int p = pos[tok % SQ];
    if (threadIdx.x < 64) {
        double freq = exp(-(double)threadIdx.x * (9.210340371976184 / 64.0));
        float ang = (float)((double)p * freq);
        float s, c;
        sincosf(ang, &s, &c);
        cs[threadIdx.x] = c;
        sn[threadIdx.x] = s;
    }
    __syncthreads();
    for (int item = threadIdx.x; item < (NH + NKV) * 64; item += blockDim.x) {
        int head = item >> 6;
        int d = item & 63;
        float c = cs[d], s = sn[d];
        float* base = qkv + (size_t)tok * QKVD + head * HDIM;
        float t1 = base[d];
        float t2 = base[d + 64];
        base[d]      = t1 * c - t2 * s;
        base[d + 64] = t2 * c + t1 * s;
    }
}

// ---------------- Tensor-core flash attention (tf32 mma, causal, GQA) ----------------
// grid (SQ/128, NH, BATCH), 256 threads (8 warps x 16 q-rows).
// smem pitches: Q/K = 132 words (bank = 4g+tg), V = 136 (bank = 8tg+g), P = 68.
// All fragment LDS are BATCHED before the mma group (latency amortization — the
// interleaved version exposed 29 cyc per LDS and ran ~10x slower).
#define QP 132
#define VP 136
#define PP 68
#define ATTN_SMEM ((128 * QP + 64 * QP + 64 * VP + 128 * PP) * 4)

__global__ __launch_bounds__(256, 1) void attn_mma_kernel(const float* __restrict__ qkv,
                                                          float* __restrict__ attn_out) {
    extern __shared__ float smem[];
    float* Qs = smem;                    // 128 x QP
    float* Ks = Qs + 128 * QP;           // 64 x QP
    float* Vs = Ks + 64 * QP;            // 64 x VP
    float* Ps = Vs + 64 * VP;            // 128 x PP

    const int qt = (gridDim.x - 1) - blockIdx.x;  // heavy tiles first (LPT)
    const int h = blockIdx.y, b = blockIdx.z;
    const int kvh = h / (NH / NKV);
    const int tid = threadIdx.x, w = tid >> 5, lane = tid & 31;
    const int g = lane >> 2, tg = lane & 3;
    const int tokQ0 = b * SQ + qt * 128;

    const uint32_t sQ = smem_u32(Qs), sK = smem_u32(Ks), sV = smem_u32(Vs),
                   sP = smem_u32(Ps);

    // load + round Q tile (128 x 128)
    for (int i = tid; i < 128 * 32; i += 256) {
        int r = i >> 5, c4 = (i & 31) * 4;
        float4 v = *(const float4*)(qkv + (size_t)(tokQ0 + r) * QKVD + h * HDIM + c4);
        v.x = tf32rnd(v.x); v.y = tf32rnd(v.y); v.z = tf32rnd(v.z); v.w = tf32rnd(v.w);
        *(float4*)(Qs + r * QP + c4) = v;
    }

    float o[16][4];
#pragma unroll
    for (int nf = 0; nf < 16; nf++)
#pragma unroll
        for (int z = 0; z < 4; z++) o[nf][z] = 0.f;
    float m0 = -1e30f, m1 = -1e30f, l0 = 0.f, l1 = 0.f;
    const float scale = 0.08838834764831845f;

    const int row0 = qt * 128 + w * 16 + g;
    const int ntile = 2 * qt + 2;

    for (int kt = 0; kt < ntile; kt++) {
        __syncthreads();
        {
            int tokK0 = b * SQ + kt * 64;
            for (int i = tid; i < 64 * 32; i += 256) {
                int r = i >> 5, c4 = (i & 31) * 4;
                const float* base = qkv + (size_t)(tokK0 + r) * QKVD;
                float4 kv = *(const float4*)(base + NH * HDIM + kvh * HDIM + c4);
                float4 vv = *(const float4*)(base + (NH + NKV) * HDIM + kvh * HDIM + c4);
                kv.x = tf32rnd(kv.x); kv.y = tf32rnd(kv.y);
                kv.z = tf32rnd(kv.z); kv.w = tf32rnd(kv.w);
                vv.x = tf32rnd(vv.x); vv.y = tf32rnd(vv.y);
                vv.z = tf32rnd(vv.z); vv.w = tf32rnd(vv.w);
                *(float4*)(Ks + r * QP + c4) = kv;
                *(float4*)(Vs + r * VP + c4) = vv;
            }
        }
        __syncthreads();

        if (kt * 64 > qt * 128 + w * 16 + 15) continue;

        // ---- S = Q @ K^T  (16 x 64, k=128), batched fragment loads ----
        float s[8][4];
#pragma unroll
        for (int nf = 0; nf < 8; nf++)
#pragma unroll
            for (int z = 0; z < 4; z++) s[nf][z] = 0.f;

        const uint32_t qrow = sQ + (uint32_t)((w * 16 + g) * QP) * 4;
#pragma unroll 4
        for (int ks = 0; ks < 16; ks++) {
            uint32_t ko = (uint32_t)(ks * 8 + tg) * 4;
            uint32_t a[4];
            a[0] = lds_u32(qrow + ko);
            a[1] = lds_u32(qrow + (uint32_t)(8 * QP) * 4 + ko);
            a[2] = lds_u32(qrow + ko + 16);
            a[3] = lds_u32(qrow + (uint32_t)(8 * QP) * 4 + ko + 16);
            uint32_t bq[8][2];
#pragma unroll
            for (int nf = 0; nf < 8; nf++) {
                uint32_t krow = sK + (uint32_t)((nf * 8 + g) * QP) * 4;
                bq[nf][0] = lds_u32(krow + ko);
                bq[nf][1] = lds_u32(krow + ko + 16);
            }
#pragma unroll
            for (int nf = 0; nf < 8; nf++)
                mma_tf32(s[nf], a, bq[nf]);
        }

        // ---- online softmax ----
        const bool domask = (kt >= 2 * qt);
        float mx0 = -1e30f, mx1 = -1e30f;
#pragma unroll
        for (int nf = 0; nf < 8; nf++) {
#pragma unroll
            for (int z = 0; z < 4; z++) {
                float v = s[nf][z] * scale;
                if (domask) {
                    int col = kt * 64 + nf * 8 + 2 * tg + (z & 1);
                    int row = (z < 2) ? row0 : row0 + 8;
                    if (col > row) v = -1e30f;
                }
                s[nf][z] = v;
            }
            mx0 = fmaxf(mx0, fmaxf(s[nf][0], s[nf][1]));
            mx1 = fmaxf(mx1, fmaxf(s[nf][2], s[nf][3]));
        }
        mx0 = fmaxf(mx0, __shfl_xor_sync(0xffffffffu, mx0, 1));
        mx0 = fmaxf(mx0, __shfl_xor_sync(0xffffffffu, mx0, 2));
        mx1 = fmaxf(mx1, __shfl_xor_sync(0xffffffffu, mx1, 1));
        mx1 = fmaxf(mx1, __shfl_xor_sync(0xffffffffu, mx1, 2));
        float mn0 = fmaxf(m0, mx0), mn1 = fmaxf(m1, mx1);
        float c0 = __expf(m0 - mn0), c1 = __expf(m1 - mn1);
        float sum0 = 0.f, sum1 = 0.f;
        float* prow0 = Ps + (w * 16 + g) * PP + 2 * tg;
        float* prow1 = prow0 + 8 * PP;
#pragma unroll
        for (int nf = 0; nf < 8; nf++) {
            float p0 = tf32rnd(__expf(s[nf][0] - mn0));
            float p1 = tf32rnd(__expf(s[nf][1] - mn0));
            float p2 = tf32rnd(__expf(s[nf][2] - mn1));
            float p3 = tf32rnd(__expf(s[nf][3] - mn1));
            sum0 += p0 + p1;
            sum1 += p2 + p3;
            *(float2*)(prow0 + nf * 8) = make_float2(p0, p1);
            *(float2*)(prow1 + nf * 8) = make_float2(p2, p3);
        }
        sum0 += __shfl_xor_sync(0xffffffffu, sum0, 1);
        sum0 += __shfl_xor_sync(0xffffffffu, sum0, 2);
        sum1 += __shfl_xor_sync(0xffffffffu, sum1, 1);
        sum1 += __shfl_xor_sync(0xffffffffu, sum1, 2);
        l0 = l0 * c0 + sum0;
        l1 = l1 * c1 + sum1;
        m0 = mn0; m1 = mn1;
#pragma unroll
        for (int nf = 0; nf < 16; nf++) {
            o[nf][0] *= c0; o[nf][1] *= c0;
            o[nf][2] *= c1; o[nf][3] *= c1;
        }
        __syncwarp();

        // ---- O += P @ V  (16 x 128, k=64), batched fragment loads ----
        const uint32_t prow = sP + (uint32_t)((w * 16 + g) * PP) * 4;
#pragma unroll 2
        for (int ks = 0; ks < 8; ks++) {
            uint32_t ko = (uint32_t)(ks * 8 + tg) * 4;
            uint32_t a[4];
            a[0] = lds_u32(prow + ko);
            a[1] = lds_u32(prow + (uint32_t)(8 * PP) * 4 + ko);
            a[2] = lds_u32(prow + ko + 16);
            a[3] = lds_u32(prow + (uint32_t)(8 * PP) * 4 + ko + 16);
            uint32_t v0 = sV + (uint32_t)((ks * 8 + tg) * VP + g) * 4;
            uint32_t v1 = sV + (uint32_t)((ks * 8 + tg + 4) * VP + g) * 4;
            uint32_t bv[16][2];
#pragma unroll
            for (int nf = 0; nf < 16; nf++) {
                bv[nf][0] = lds_u32(v0 + nf * 32);
                bv[nf][1] = lds_u32(v1 + nf * 32);
            }
#pragma unroll
            for (int nf = 0; nf < 16; nf++)
                mma_tf32(o[nf], a, bv[nf]);
        }
    }

    // ---- epilogue ----
    float inv0 = 1.f / l0, inv1 = 1.f / l1;
    float* orow0 = attn_out + (size_t)(tokQ0 + w * 16 + g) * HIDD + h * HDIM;
    float* orow1 = orow0 + (size_t)8 * HIDD;
#pragma unroll
    for (int nf = 0; nf < 16; nf++) {
        int col = nf * 8 + 2 * tg;
        *(float2*)(orow0 + col) = make_float2(tf32rnd(o[nf][0] * inv0),
                                              tf32rnd(o[nf][1] * inv0));
        *(float2*)(orow1 + col) = make_float2(tf32rnd(o[nf][2] * inv1),
                                              tf32rnd(o[nf][3] * inv1));
    }
}

// ---------------- SiLU(gate) * up (output tf32-rounded) ----------------
__global__ void silu_kernel(const float* __restrict__ gu, float* __restrict__ act) {
    size_t n4 = (size_t)NTOK * INTD / 4;
    for (size_t idx = (size_t)blockIdx.x * blockDim.x + threadIdx.x; idx < n4;
         idx += (size_t)gridDim.x * blockDim.x) {
        size_t t = idx / (INTD / 4);
        size_t c = (idx % (INTD / 4)) * 4;
        float4 g = *(const float4*)(gu + t * (2 * INTD) + c);
        float4 u = *(const float4*)(gu + t * (2 * INTD) + INTD + c);
        float4 o;
        o.x = tf32rnd(g.x / (1.f + __expf(-g.x)) * u.x);
        o.y = tf32rnd(g.y / (1.f + __expf(-g.y)) * u.y);
        o.z = tf32rnd(g.z / (1.f + __expf(-g.z)) * u.z);
        o.w = tf32rnd(g.w / (1.f + __expf(-g.w)) * u.w);
        *(float4*)(act + idx * 4) = o;
    }
}

extern "C" void kernel_launch(void* const* d_in, const int* in_sizes, int n_in,
                              void* d_out, int out_size) {
    const float* x    = (const float*)d_in[0];
    const float* ln1  = (const float*)d_in[1];
    const float* wqkv = (const float*)d_in[2];
    const float* wo   = (const float*)d_in[3];
    const float* ln2  = (const float*)d_in[4];
    const float* wgu  = (const float*)d_in[5];
    const float* wdn  = (const float*)d_in[6];
    const int*   pos  = (const int*)d_in[7];
    float* out = (float*)d_out;

    void *xn, *qkv, *attn, *h1, *h2, *gu, *act;
    void *wqkvT, *woT, *wguT, *wdnT;
    cudaGetSymbolAddress(&xn, g_xn);
    cudaGetSymbolAddress(&qkv, g_qkv);
    cudaGetSymbolAddress(&attn, g_attn);
    cudaGetSymbolAddress(&h1, g_h1);
    cudaGetSymbolAddress(&h2, g_h2);
    cudaGetSymbolAddress(&gu, g_gu);
    cudaGetSymbolAddress(&act, g_act);
    cudaGetSymbolAddress(&wqkvT, g_wqkvT);
    cudaGetSymbolAddress(&woT, g_woT);
    cudaGetSymbolAddress(&wguT, g_wguT);
    cudaGetSymbolAddress(&wdnT, g_wdnT);

    cudaFuncSetAttribute(attn_mma_kernel, cudaFuncAttributeMaxDynamicSharedMemorySize, ATTN_SMEM);
    cudaFuncSetAttribute(tc_gemm<false>, cudaFuncAttributeMaxDynamicSharedMemorySize, GEMM_SMEM_TC);
    cudaFuncSetAttribute(tc_gemm<true>,  cudaFuncAttributeMaxDynamicSharedMemorySize, GEMM_SMEM_TC);

    // 0. weight transpose + tf32 rounding
    {
        dim3 bb(32, 8);
        transpose_round_kernel<<<dim3(QKVD / 32, HIDD / 32), bb>>>(wqkv, (float*)wqkvT, HIDD, QKVD);
        transpose_round_kernel<<<dim3(HIDD / 32, HIDD / 32), bb>>>(wo, (float*)woT, HIDD, HIDD);
        transpose_round_kernel<<<dim3(2 * INTD / 32, HIDD / 32), bb>>>(wgu, (float*)wguT, HIDD, 2 * INTD);
        transpose_round_kernel<<<dim3(HIDD / 32, INTD / 32), bb>>>(wdn, (float*)wdnT, INTD, HIDD);
    }
    // 1. h = rmsnorm(x, ln1)
    rmsnorm_kernel<<<NTOK, 256>>>(x, ln1, (float*)xn);
    // 2. qkv = h @ wqkv
    tc_gemm<false><<<dim3(NTOK / TM, QKVD / TN), 256, GEMM_SMEM_TC>>>(
        (const float*)xn, (const float*)wqkvT, nullptr, (float*)qkv, QKVD, HIDD);
    // 3. RoPE
    rope_kernel<<<NTOK, 256>>>((float*)qkv, pos);
    // 4. attention (tensor-core, batched fragment loads)
    {
        dim3 g(SQ / 128, NH, BATCH);
        attn_mma_kernel<<<g, 256, ATTN_SMEM>>>((const float*)qkv, (float*)attn);
    }
    // 5. h1 = x + attn @ wo
    tc_gemm<true><<<dim3(NTOK / TM, HIDD / TN), 256, GEMM_SMEM_TC>>>(
        (const float*)attn, (const float*)woT, x, (float*)h1, HIDD, HIDD);
    // 6. h2 = rmsnorm(h1, ln2)
    rmsnorm_kernel<<<NTOK, 256>>>((const float*)h1, ln2, (float*)h2);
    // 7. gu = h2 @ w_gate_up
    tc_gemm<false><<<dim3(NTOK / TM, 2 * INTD / TN), 256, GEMM_SMEM_TC>>>(
        (const float*)h2, (const float*)wguT, nullptr, (float*)gu, 2 * INTD, HIDD);
    // 8. act = silu(gate)*up
    silu_kernel<<<2048, 256>>>((const float*)gu, (float*)act);
    // 9. out = h1 + act @ w_down
    tc_gemm<true><<<dim3(NTOK / TM, HIDD / TN), 256, GEMM_SMEM_TC>>>(
        (const float*)act, (const float*)wdnT, (const float*)h1, out, HIDD, INTD);
}

// round 8
// speedup vs baseline: 1.6074x; 1.0525x over previous
#include <cuda_runtime.h>
#include <cuda_bf16.h>
#include <math.h>
#include <stdint.h>

#define NTOK 4096
#define SQ   1024
#define BATCH 4
#define HIDD 2048
#define NH   16
#define NKV  4
#define HDIM 128
#define QKVD 3072   // (16+2*4)*128
#define INTD 8192

// ---------------- scratch (static device memory; no allocations) ----------------
__device__ float g_xn  [(size_t)NTOK * HIDD];
__device__ float g_qkv [(size_t)NTOK * QKVD];
__device__ float g_attn[(size_t)NTOK * HIDD];
__device__ float g_h1  [(size_t)NTOK * HIDD];
__device__ float g_h2  [(size_t)NTOK * HIDD];
__device__ float g_act [(size_t)NTOK * INTD];
// transposed + tf32-rounded weights [N, K] K-major
__device__ float g_wqkvT [(size_t)QKVD * HIDD];
__device__ float g_woT   [(size_t)HIDD * HIDD];
__device__ float g_wguT  [(size_t)2 * INTD * HIDD];  // interleaved: row 2j=gate_j, 2j+1=up_j
__device__ float g_wdnT  [(size_t)HIDD * INTD];

// ---------------- helpers ----------------
__device__ __forceinline__ float tf32rnd(float x) {
    uint32_t u;
    asm("cvt.rna.tf32.f32 %0, %1;" : "=r"(u) : "f"(x));
    return __uint_as_float(u);
}

__device__ __forceinline__ uint32_t smem_u32(const void* p) {
    uint32_t a;
    asm("{ .reg .u64 t; cvta.to.shared.u64 t, %1; cvt.u32.u64 %0, t; }"
        : "=r"(a) : "l"(p));
    return a;
}

__device__ __forceinline__ uint32_t lds_u32(uint32_t a) {
    uint32_t v;
    asm volatile("ld.shared.b32 %0, [%1];" : "=r"(v) : "r"(a));
    return v;
}

#define SWZ128(o) ((o) ^ (((o) >> 3) & 0x70))

#define CP_ASYNC16(dst, src) \
    asm volatile("cp.async.cg.shared.global [%0], [%1], 16;" :: "r"(dst), "l"(src) : "memory")
#define CP_COMMIT() asm volatile("cp.async.commit_group;" ::: "memory")

__device__ __forceinline__ void mma_tf32(float* c, const uint32_t* a, const uint32_t* b) {
    asm volatile(
        "mma.sync.aligned.m16n8k8.row.col.f32.tf32.tf32.f32 "
        "{%0,%1,%2,%3}, {%4,%5,%6,%7}, {%8,%9}, {%0,%1,%2,%3};\n"
        : "+f"(c[0]), "+f"(c[1]), "+f"(c[2]), "+f"(c[3])
        : "r"(a[0]), "r"(a[1]), "r"(a[2]), "r"(a[3]), "r"(b[0]), "r"(b[1]));
}

// ---------------- HMMA tf32 GEMM: tile 256(M) x 128(N), kc=32, 3-stage cp.async --------
// MODE: 0 = plain C=A@Bt^T, 1 = C = R + A@Bt^T, 2 = silu-fused (interleaved gate/up cols,
//       writes act[M, N/2] = silu(even)*odd, tf32-rounded)
#define TM 256
#define TN 128
#define KC 32
#define NSTG 3
#define ASZ (TM * KC * 4)
#define BSZ (TN * KC * 4)
#define STGB (ASZ + BSZ)
#define GEMM_SMEM_TC (NSTG * STGB)

template <int MODE>
__global__ __launch_bounds__(256, 1) void tc_gemm(const float* __restrict__ A,
                                                  const float* __restrict__ Bt,
                                                  const float* __restrict__ R,
                                                  float* __restrict__ C,
                                                  int N, int K) {
    extern __shared__ char smc[];
    const uint32_t sb = smem_u32(smc);
    const int tid = threadIdx.x;
    const int lane = tid & 31, w = tid >> 5;
    const int wm = w >> 1, wn = w & 1;
    const int g = lane >> 2, tg = lane & 3;
    const int by = blockIdx.x, bx = blockIdx.y;

    const float* Ab = A + (size_t)(by * TM) * K;
    const float* Bb = Bt + (size_t)(bx * TN) * K;
    const int nk = K / KC;

    const int lrow = tid >> 3;
    const int lseg = tid & 7;

    float acc[4][8][4];
#pragma unroll
    for (int i = 0; i < 4; i++)
#pragma unroll
        for (int j = 0; j < 8; j++)
#pragma unroll
            for (int z = 0; z < 4; z++) acc[i][j][z] = 0.f;

    auto load_chunk = [&](int j) {
        uint32_t st = sb + (j % NSTG) * STGB;
#pragma unroll
        for (int i = 0; i < 8; i++) {
            int r = i * 32 + lrow;
            uint32_t off = (uint32_t)(r * 128 + lseg * 16);
            CP_ASYNC16(st + SWZ128(off), Ab + (size_t)r * K + j * KC + lseg * 4);
        }
        uint32_t stB = st + ASZ;
#pragma unroll
        for (int i = 0; i < 4; i++) {
            int r = i * 32 + lrow;
            uint32_t off = (uint32_t)(r * 128 + lseg * 16);
            CP_ASYNC16(stB + SWZ128(off), Bb + (size_t)r * K + j * KC + lseg * 4);
        }
        CP_COMMIT();
    };

    for (int j = 0; j < NSTG - 1 && j < nk; j++) load_chunk(j);

    for (int it = 0; it < nk; it++) {
        if (it < nk - 1)
            asm volatile("cp.async.wait_group 1;" ::: "memory");
        else
            asm volatile("cp.async.wait_group 0;" ::: "memory");
        __syncthreads();   // single sync per k-tile: orders reads of buf (it-1) before its reuse
        if (it + NSTG - 1 < nk) load_chunk(it + NSTG - 1);

        const uint32_t sA = sb + (it % NSTG) * STGB;
        const uint32_t sB = sA + ASZ;
#pragma unroll
        for (int kk = 0; kk < 4; kk++) {
            const int k0 = kk * 8;
            uint32_t af[4][4];
#pragma unroll
            for (int mf = 0; mf < 4; mf++) {
                int r0 = wm * 64 + mf * 16 + g;
                uint32_t ro = sA + r0 * 128;
                uint32_t kx = (uint32_t)((r0 & 7) << 4);
                uint32_t kl = ((uint32_t)((k0 + tg) * 4)) ^ kx;
                uint32_t kh = ((uint32_t)((k0 + tg + 4) * 4)) ^ kx;
                af[mf][0] = lds_u32(ro + kl);
                af[mf][1] = lds_u32(ro + 1024 + kl);
                af[mf][2] = lds_u32(ro + kh);
                af[mf][3] = lds_u32(ro + 1024 + kh);
            }
            uint32_t bf[8][2];
#pragma unroll
            for (int nf = 0; nf < 8; nf++) {
                int r = wn * 64 + nf * 8 + g;
                uint32_t ro = sB + r * 128;
                uint32_t kx = (uint32_t)((r & 7) << 4);
                bf[nf][0] = lds_u32(ro + (((uint32_t)((k0 + tg) * 4)) ^ kx));
                bf[nf][1] = lds_u32(ro + (((uint32_t)((k0 + tg + 4) * 4)) ^ kx));
            }
#pragma unroll
            for (int mf = 0; mf < 4; mf++)
#pragma unroll
                for (int nf = 0; nf < 8; nf++)
                    mma_tf32(acc[mf][nf], af[mf], bf[nf]);
        }
    }

    // ---- epilogue ----
#pragma unroll
    for (int mf = 0; mf < 4; mf++) {
#pragma unroll
        for (int half = 0; half < 2; half++) {
            int row = by * TM + wm * 64 + mf * 16 + g + half * 8;
            if (MODE == 2) {
                // interleaved gate/up: acc pair (even,odd) = (gate, up) for one element
                float* Arow = C + (size_t)row * (N / 2) + bx * (TN / 2) + wn * 32;
#pragma unroll
                for (int nf = 0; nf < 8; nf++) {
                    float gv = acc[mf][nf][half * 2 + 0];
                    float uv = acc[mf][nf][half * 2 + 1];
                    Arow[nf * 4 + tg] = tf32rnd(gv / (1.f + __expf(-gv)) * uv);
                }
            } else {
                float* Crow = C + (size_t)row * N + bx * TN + wn * 64;
                const float* Rrow = (MODE == 1)
                    ? (R + (size_t)row * N + bx * TN + wn * 64) : (const float*)0;
#pragma unroll
                for (int nf = 0; nf < 8; nf++) {
                    int col = nf * 8 + tg * 2;
                    float2 v = make_float2(acc[mf][nf][half * 2 + 0],
                                           acc[mf][nf][half * 2 + 1]);
                    if (MODE == 1) {
                        v.x += Rrow[col];
                        v.y += Rrow[col + 1];
                    }
                    *(float2*)(Crow + col) = v;
                }
            }
        }
    }
}

// ---------------- weight transpose + tf32 round ----------------
// INTERLEAVE=0: out[n][k] = rnd(in[k][n]).
// INTERLEAVE=1 (gate_up): out row 2j = in col j (gate), row 2j+1 = in col j+INTD (up).
template <int INTERLEAVE>
__global__ void transpose_round_kernel(const float* __restrict__ in,
                                       float* __restrict__ out, int K, int N) {
    __shared__ float t[32][33];
    int n0 = blockIdx.x * 32, k0 = blockIdx.y * 32;
    int tx = threadIdx.x, ty = threadIdx.y;
#pragma unroll
    for (int r = 0; r < 4; r++)
        t[ty + r * 8][tx] = in[(size_t)(k0 + ty + r * 8) * N + n0 + tx];
    __syncthreads();
#pragma unroll
    for (int r = 0; r < 4; r++) {
        int n = n0 + ty + r * 8;
        size_t rowI;
        if (INTERLEAVE)
            rowI = (n < INTD) ? (size_t)(2 * n) : (size_t)(2 * (n - INTD) + 1);
        else
            rowI = (size_t)n;
        out[rowI * K + k0 + tx] = tf32rnd(t[tx][ty + r * 8]);
    }
}

// ---------------- RMSNorm (output tf32-rounded) ----------------
__global__ void rmsnorm_kernel(const float* __restrict__ x, const float* __restrict__ w,
                               float* __restrict__ out) {
    int row = blockIdx.x;
    const float* xr = x + (size_t)row * HIDD;
    __shared__ float red[256];
    float4 vals[2];
    float s = 0.f;
#pragma unroll
    for (int i = 0; i < 2; i++) {
        float4 v = *(const float4*)(xr + (threadIdx.x + i * 256) * 4);
        vals[i] = v;
        s += v.x * v.x + v.y * v.y + v.z * v.z + v.w * v.w;
    }
    red[threadIdx.x] = s;
    __syncthreads();
    for (int off = 128; off > 0; off >>= 1) {
        if (threadIdx.x < off) red[threadIdx.x] += red[threadIdx.x + off];
        __syncthreads();
    }
    float inv = rsqrtf(red[0] / (float)HIDD + 1e-6f);
#pragma unroll
    for (int i = 0; i < 2; i++) {
        int c = (threadIdx.x + i * 256) * 4;
        float4 v = vals[i];
        float4 wv = *(const float4*)(w + c);
        float4 o = make_float4(tf32rnd(v.x * inv * wv.x), tf32rnd(v.y * inv * wv.y),
                               tf32rnd(v.z * inv * wv.z), tf32rnd(v.w * inv * wv.w));
        *(float4*)(out + (size_t)row * HIDD + c) = o;
    }
}

// ---------------- RoPE ----------------
__global__ void rope_kernel(float* __restrict__ qkv, const int* __restrict__ pos) {
    __shared__ float cs[64], sn[64];
    int tok = blockIdx.x;
    int p = pos[tok % SQ];
    if (threadIdx.x < 64) {
        double freq = exp(-(double)threadIdx.x * (9.210340371976184 / 64.0));
        float ang = (float)((double)p * freq);
        float s, c;
        sincosf(ang, &s, &c);
        cs[threadIdx.x] = c;
        sn[threadIdx.x] = s;
    }
    __syncthreads();
    for (int item = threadIdx.x; item < (NH + NKV) * 64; item += blockDim.x) {
        int head = item >> 6;
        int d = item & 63;
        float c = cs[d], s = sn[d];
        float* base = qkv + (size_t)tok * QKVD + head * HDIM;
        float t1 = base[d];
        float t2 = base[d + 64];
        base[d]      = t1 * c - t2 * s;
        base[d + 64] = t2 * c + t1 * s;
    }
}

// ---------------- Tensor-core flash attention (tf32 mma, causal, GQA) ----------------
#define QP 132
#define VP 136
#define PP 68
#define ATTN_SMEM ((128 * QP + 64 * QP + 64 * VP + 128 * PP) * 4)

__global__ __launch_bounds__(256, 1) void attn_mma_kernel(const float* __restrict__ qkv,
                                                          float* __restrict__ attn_out) {
    extern __shared__ float smem[];
    float* Qs = smem;                    // 128 x QP
    float* Ks = Qs + 128 * QP;           // 64 x QP
    float* Vs = Ks + 64 * QP;            // 64 x VP
    float* Ps = Vs + 64 * VP;            // 128 x PP

    const int qt = (gridDim.x - 1) - blockIdx.x;
    const int h = blockIdx.y, b = blockIdx.z;
    const int kvh = h / (NH / NKV);
    const int tid = threadIdx.x, w = tid >> 5, lane = tid & 31;
    const int g = lane >> 2, tg = lane & 3;
    const int tokQ0 = b * SQ + qt * 128;

    const uint32_t sQ = smem_u32(Qs), sK = smem_u32(Ks), sV = smem_u32(Vs),
                   sP = smem_u32(Ps);

    for (int i = tid; i < 128 * 32; i += 256) {
        int r = i >> 5, c4 = (i & 31) * 4;
        float4 v = *(const float4*)(qkv + (size_t)(tokQ0 + r) * QKVD + h * HDIM + c4);
        v.x = tf32rnd(v.x); v.y = tf32rnd(v.y); v.z = tf32rnd(v.z); v.w = tf32rnd(v.w);
        *(float4*)(Qs + r * QP + c4) = v;
    }

    float o[16][4];
#pragma unroll
    for (int nf = 0; nf < 16; nf++)
#pragma unroll
        for (int z = 0; z < 4; z++) o[nf][z] = 0.f;
    float m0 = -1e30f, m1 = -1e30f, l0 = 0.f, l1 = 0.f;
    const float scale = 0.08838834764831845f;

    const int row0 = qt * 128 + w * 16 + g;
    const int ntile = 2 * qt + 2;

    for (int kt = 0; kt < ntile; kt++) {
        __syncthreads();
        {
            int tokK0 = b * SQ + kt * 64;
            for (int i = tid; i < 64 * 32; i += 256) {
                int r = i >> 5, c4 = (i & 31) * 4;
                const float* base = qkv + (size_t)(tokK0 + r) * QKVD;
                float4 kv = *(const float4*)(base + NH * HDIM + kvh * HDIM + c4);
                float4 vv = *(const float4*)(base + (NH + NKV) * HDIM + kvh * HDIM + c4);
                kv.x = tf32rnd(kv.x); kv.y = tf32rnd(kv.y);
                kv.z = tf32rnd(kv.z); kv.w = tf32rnd(kv.w);
                vv.x = tf32rnd(vv.x); vv.y = tf32rnd(vv.y);
                vv.z = tf32rnd(vv.z); vv.w = tf32rnd(vv.w);
                *(float4*)(Ks + r * QP + c4) = kv;
                *(float4*)(Vs + r * VP + c4) = vv;
            }
        }
        __syncthreads();

        if (kt * 64 > qt * 128 + w * 16 + 15) continue;

        float s[8][4];
#pragma unroll
        for (int nf = 0; nf < 8; nf++)
#pragma unroll
            for (int z = 0; z < 4; z++) s[nf][z] = 0.f;

        const uint32_t qrow = sQ + (uint32_t)((w * 16 + g) * QP) * 4;
#pragma unroll 4
        for (int ks = 0; ks < 16; ks++) {
            uint32_t ko = (uint32_t)(ks * 8 + tg) * 4;
            uint32_t a[4];
            a[0] = lds_u32(qrow + ko);
            a[1] = lds_u32(qrow + (uint32_t)(8 * QP) * 4 + ko);
            a[2] = lds_u32(qrow + ko + 16);
            a[3] = lds_u32(qrow + (uint32_t)(8 * QP) * 4 + ko + 16);
            uint32_t bq[8][2];
#pragma unroll
            for (int nf = 0; nf < 8; nf++) {
                uint32_t krow = sK + (uint32_t)((nf * 8 + g) * QP) * 4;
                bq[nf][0] = lds_u32(krow + ko);
                bq[nf][1] = lds_u32(krow + ko + 16);
            }
#pragma unroll
            for (int nf = 0; nf < 8; nf++)
                mma_tf32(s[nf], a, bq[nf]);
        }

        const bool domask = (kt >= 2 * qt);
        float mx0 = -1e30f, mx1 = -1e30f;
#pragma unroll
        for (int nf = 0; nf < 8; nf++) {
#pragma unroll
            for (int z = 0; z < 4; z++) {
                float v = s[nf][z] * scale;
                if (domask) {
                    int col = kt * 64 + nf * 8 + 2 * tg + (z & 1);
                    int row = (z < 2) ? row0 : row0 + 8;
                    if (col > row) v = -1e30f;
                }
                s[nf][z] = v;
            }
            mx0 = fmaxf(mx0, fmaxf(s[nf][0], s[nf][1]));
            mx1 = fmaxf(mx1, fmaxf(s[nf][2], s[nf][3]));
        }
        mx0 = fmaxf(mx0, __shfl_xor_sync(0xffffffffu, mx0, 1));
        mx0 = fmaxf(mx0, __shfl_xor_sync(0xffffffffu, mx0, 2));
        mx1 = fmaxf(mx1, __shfl_xor_sync(0xffffffffu, mx1, 1));
        mx1 = fmaxf(mx1, __shfl_xor_sync(0xffffffffu, mx1, 2));
        float mn0 = fmaxf(m0, mx0), mn1 = fmaxf(m1, mx1);
        float c0 = __expf(m0 - mn0), c1 = __expf(m1 - mn1);
        float sum0 = 0.f, sum1 = 0.f;
        float* prow0 = Ps + (w * 16 + g) * PP + 2 * tg;
        float* prow1 = prow0 + 8 * PP;
#pragma unroll
        for (int nf = 0; nf < 8; nf++) {
            float p0 = tf32rnd(__expf(s[nf][0] - mn0));
            float p1 = tf32rnd(__expf(s[nf][1] - mn0));
            float p2 = tf32rnd(__expf(s[nf][2] - mn1));
            float p3 = tf32rnd(__expf(s[nf][3] - mn1));
            sum0 += p0 + p1;
            sum1 += p2 + p3;
            *(float2*)(prow0 + nf * 8) = make_float2(p0, p1);
            *(float2*)(prow1 + nf * 8) = make_float2(p2, p3);
        }
        sum0 += __shfl_xor_sync(0xffffffffu, sum0, 1);
        sum0 += __shfl_xor_sync(0xffffffffu, sum0, 2);
        sum1 += __shfl_xor_sync(0xffffffffu, sum1, 1);
        sum1 += __shfl_xor_sync(0xffffffffu, sum1, 2);
        l0 = l0 * c0 + sum0;
        l1 = l1 * c1 + sum1;
        m0 = mn0; m1 = mn1;
#pragma unroll
        for (int nf = 0; nf < 16; nf++) {
            o[nf][0] *= c0; o[nf][1] *= c0;
            o[nf][2] *= c1; o[nf][3] *= c1;
        }
        __syncwarp();

        const uint32_t prow = sP + (uint32_t)((w * 16 + g) * PP) * 4;
#pragma unroll 2
        for (int ks = 0; ks < 8; ks++) {
            uint32_t ko = (uint32_t)(ks * 8 + tg) * 4;
            uint32_t a[4];
            a[0] = lds_u32(prow + ko);
            a[1] = lds_u32(prow + (uint32_t)(8 * PP) * 4 + ko);
            a[2] = lds_u32(prow + ko + 16);
            a[3] = lds_u32(prow + (uint32_t)(8 * PP) * 4 + ko + 16);
            uint32_t v0 = sV + (uint32_t)((ks * 8 + tg) * VP + g) * 4;
            uint32_t v1 = sV + (uint32_t)((ks * 8 + tg + 4) * VP + g) * 4;
            uint32_t bv[16][2];
#pragma unroll
            for (int nf = 0; nf < 16; nf++) {
                bv[nf][0] = lds_u32(v0 + nf * 32);
                bv[nf][1] = lds_u32(v1 + nf * 32);
            }
#pragma unroll
            for (int nf = 0; nf < 16; nf++)
                mma_tf32(o[nf], a, bv[nf]);
        }
    }

    float inv0 = 1.f / l0, inv1 = 1.f / l1;
    float* orow0 = attn_out + (size_t)(tokQ0 + w * 16 + g) * HIDD + h * HDIM;
    float* orow1 = orow0 + (size_t)8 * HIDD;
#pragma unroll
    for (int nf = 0; nf < 16; nf++) {
        int col = nf * 8 + 2 * tg;
        *(float2*)(orow0 + col) = make_float2(tf32rnd(o[nf][0] * inv0),
                                              tf32rnd(o[nf][1] * inv0));
        *(float2*)(orow1 + col) = make_float2(tf32rnd(o[nf][2] * inv1),
                                              tf32rnd(o[nf][3] * inv1));
    }
}

extern "C" void kernel_launch(void* const* d_in, const int* in_sizes, int n_in,
                              void* d_out, int out_size) {
    const float* x    = (const float*)d_in[0];
    const float* ln1  = (const float*)d_in[1];
    const float* wqkv = (const float*)d_in[2];
    const float* wo   = (const float*)d_in[3];
    const float* ln2  = (const float*)d_in[4];
    const float* wgu  = (const float*)d_in[5];
    const float* wdn  = (const float*)d_in[6];
    const int*   pos  = (const int*)d_in[7];
    float* out = (float*)d_out;

    void *xn, *qkv, *attn, *h1, *h2, *act;
    void *wqkvT, *woT, *wguT, *wdnT;
    cudaGetSymbolAddress(&xn, g_xn);
    cudaGetSymbolAddress(&qkv, g_qkv);
    cudaGetSymbolAddress(&attn, g_attn);
    cudaGetSymbolAddress(&h1, g_h1);
    cudaGetSymbolAddress(&h2, g_h2);
    cudaGetSymbolAddress(&act, g_act);
    cudaGetSymbolAddress(&wqkvT, g_wqkvT);
    cudaGetSymbolAddress(&woT, g_woT);
    cudaGetSymbolAddress(&wguT, g_wguT);
    cudaGetSymbolAddress(&wdnT, g_wdnT);

    cudaFuncSetAttribute(attn_mma_kernel, cudaFuncAttributeMaxDynamicSharedMemorySize, ATTN_SMEM);
    cudaFuncSetAttribute(tc_gemm<0>, cudaFuncAttributeMaxDynamicSharedMemorySize, GEMM_SMEM_TC);
    cudaFuncSetAttribute(tc_gemm<1>, cudaFuncAttributeMaxDynamicSharedMemorySize, GEMM_SMEM_TC);
    cudaFuncSetAttribute(tc_gemm<2>, cudaFuncAttributeMaxDynamicSharedMemorySize, GEMM_SMEM_TC);

    // 0. weight transpose + tf32 rounding (gate_up interleaved)
    {
        dim3 bb(32, 8);
        transpose_round_kernel<0><<<dim3(QKVD / 32, HIDD / 32), bb>>>(wqkv, (float*)wqkvT, HIDD, QKVD);
        transpose_round_kernel<0><<<dim3(HIDD / 32, HIDD / 32), bb>>>(wo, (float*)woT, HIDD, HIDD);
        transpose_round_kernel<1><<<dim3(2 * INTD / 32, HIDD / 32), bb>>>(wgu, (float*)wguT, HIDD, 2 * INTD);
        transpose_round_kernel<0><<<dim3(HIDD / 32, INTD / 32), bb>>>(wdn, (float*)wdnT, INTD, HIDD);
    }
    // 1. h = rmsnorm(x, ln1)
    rmsnorm_kernel<<<NTOK, 256>>>(x, ln1, (float*)xn);
    // 2. qkv = h @ wqkv
    tc_gemm<0><<<dim3(NTOK / TM, QKVD / TN), 256, GEMM_SMEM_TC>>>(
        (const float*)xn, (const float*)wqkvT, nullptr, (float*)qkv, QKVD, HIDD);
    // 3. RoPE
    rope_kernel<<<NTOK, 256>>>((float*)qkv, pos);
    // 4. attention
    {
        dim3 g(SQ / 128, NH, BATCH);
        attn_mma_kernel<<<g, 256, ATTN_SMEM>>>((const float*)qkv, (float*)attn);
    }
    // 5. h1 = x + attn @ wo
    tc_gemm<1><<<dim3(NTOK / TM, HIDD / TN), 256, GEMM_SMEM_TC>>>(
        (const float*)attn, (const float*)woT, x, (float*)h1, HIDD, HIDD);
    // 6. h2 = rmsnorm(h1, ln2)
    rmsnorm_kernel<<<NTOK, 256>>>((const float*)h1, ln2, (float*)h2);
    // 7+8. act = silu(h2 @ w_gate) * (h2 @ w_up)  — fused epilogue
    tc_gemm<2><<<dim3(NTOK / TM, 2 * INTD / TN), 256, GEMM_SMEM_TC>>>(
        (const float*)h2, (const float*)wguT, nullptr, (float*)act, 2 * INTD, HIDD);
    // 9. out = h1 + act @ w_down
    tc_gemm<1><<<dim3(NTOK / TM, HIDD / TN), 256, GEMM_SMEM_TC>>>(
        (const float*)act, (const float*)wdnT, (const float*)h1, out, HIDD, INTD);
}

// round 9
// speedup vs baseline: 1.8624x; 1.1586x over previous
#include <cuda_runtime.h>
#include <cuda_bf16.h>
#include <math.h>
#include <stdint.h>

#define NTOK 4096
#define SQ   1024
#define BATCH 4
#define HIDD 2048
#define NH   16
#define NKV  4
#define HDIM 128
#define QKVD 3072   // (16+2*4)*128
#define INTD 8192

// ---------------- scratch (static device memory; no allocations) ----------------
__device__ float g_xn  [(size_t)NTOK * HIDD];
__device__ float g_qkv [(size_t)NTOK * QKVD];
__device__ float g_attn[(size_t)NTOK * HIDD];
__device__ float g_h1  [(size_t)NTOK * HIDD];
__device__ float g_h2  [(size_t)NTOK * HIDD];
__device__ float g_act [(size_t)NTOK * INTD];
// transposed + tf32-rounded weights [N, K] K-major
__device__ float g_wqkvT [(size_t)QKVD * HIDD];
__device__ float g_woT   [(size_t)HIDD * HIDD];
__device__ float g_wguT  [(size_t)2 * INTD * HIDD];  // interleaved: row 2j=gate_j, 2j+1=up_j
__device__ float g_wdnT  [(size_t)HIDD * INTD];

// ---------------- helpers ----------------
__device__ __forceinline__ float tf32rnd(float x) {
    uint32_t u;
    asm("cvt.rna.tf32.f32 %0, %1;" : "=r"(u) : "f"(x));
    return __uint_as_float(u);
}

__device__ __forceinline__ uint32_t smem_u32(const void* p) {
    uint32_t a;
    asm("{ .reg .u64 t; cvta.to.shared.u64 t, %1; cvt.u32.u64 %0, t; }"
        : "=r"(a) : "l"(p));
    return a;
}

__device__ __forceinline__ uint32_t lds_u32(uint32_t a) {
    uint32_t v;
    asm volatile("ld.shared.b32 %0, [%1];" : "=r"(v) : "r"(a));
    return v;
}

#define SWZ128(o) ((o) ^ (((o) >> 3) & 0x70))

#define CP_ASYNC16(dst, src) \
    asm volatile("cp.async.cg.shared.global [%0], [%1], 16;" :: "r"(dst), "l"(src) : "memory")
#define CP_COMMIT() asm volatile("cp.async.commit_group;" ::: "memory")

__device__ __forceinline__ void mma_tf32(float* c, const uint32_t* a, const uint32_t* b) {
    asm volatile(
        "mma.sync.aligned.m16n8k8.row.col.f32.tf32.tf32.f32 "
        "{%0,%1,%2,%3}, {%4,%5,%6,%7}, {%8,%9}, {%0,%1,%2,%3};\n"
        : "+f"(c[0]), "+f"(c[1]), "+f"(c[2]), "+f"(c[3])
        : "r"(a[0]), "r"(a[1]), "r"(a[2]), "r"(a[3]), "r"(b[0]), "r"(b[1]));
}

// ---------------- HMMA tf32 GEMM: tile 256(M) x 128(N), kc=32, 4-stage, 2 chunks/sync --
// MODE: 0 = plain, 1 = +residual, 2 = silu-fused (interleaved gate/up)
#define TM 256
#define TN 128
#define KC 32
#define NSTG 4
#define ASZ (TM * KC * 4)
#define BSZ (TN * KC * 4)
#define STGB (ASZ + BSZ)
#define GEMM_SMEM_TC (NSTG * STGB)   // 196608 B

template <int MODE>
__global__ __launch_bounds__(256, 1) void tc_gemm(const float* __restrict__ A,
                                                  const float* __restrict__ Bt,
                                                  const float* __restrict__ R,
                                                  float* __restrict__ C,
                                                  int N, int K) {
    extern __shared__ char smc[];
    const uint32_t sb = smem_u32(smc);
    const int tid = threadIdx.x;
    const int lane = tid & 31, w = tid >> 5;
    const int wm = w >> 1, wn = w & 1;
    const int g = lane >> 2, tg = lane & 3;
    const int by = blockIdx.x, bx = blockIdx.y;

    const float* Ab = A + (size_t)(by * TM) * K;
    const float* Bb = Bt + (size_t)(bx * TN) * K;
    const int nk = K / KC;   // always even here

    const int lrow = tid >> 3;
    const int lseg = tid & 7;

    float acc[4][8][4];
#pragma unroll
    for (int i = 0; i < 4; i++)
#pragma unroll
        for (int j = 0; j < 8; j++)
#pragma unroll
            for (int z = 0; z < 4; z++) acc[i][j][z] = 0.f;

    auto load_chunk = [&](int j) {
        uint32_t st = sb + (j & 3) * STGB;
#pragma unroll
        for (int i = 0; i < 8; i++) {
            int r = i * 32 + lrow;
            uint32_t off = (uint32_t)(r * 128 + lseg * 16);
            CP_ASYNC16(st + SWZ128(off), Ab + (size_t)r * K + j * KC + lseg * 4);
        }
        uint32_t stB = st + ASZ;
#pragma unroll
        for (int i = 0; i < 4; i++) {
            int r = i * 32 + lrow;
            uint32_t off = (uint32_t)(r * 128 + lseg * 16);
            CP_ASYNC16(stB + SWZ128(off), Bb + (size_t)r * K + j * KC + lseg * 4);
        }
        CP_COMMIT();
    };

    auto compute_chunk = [&](int it) {
        const uint32_t sA = sb + (it & 3) * STGB;
        const uint32_t sB = sA + ASZ;
#pragma unroll
        for (int kk = 0; kk < 4; kk++) {
            const int k0 = kk * 8;
            uint32_t af[4][4];
#pragma unroll
            for (int mf = 0; mf < 4; mf++) {
                int r0 = wm * 64 + mf * 16 + g;
                uint32_t ro = sA + r0 * 128;
                uint32_t kx = (uint32_t)((r0 & 7) << 4);
                uint32_t kl = ((uint32_t)((k0 + tg) * 4)) ^ kx;
                uint32_t kh = ((uint32_t)((k0 + tg + 4) * 4)) ^ kx;
                af[mf][0] = lds_u32(ro + kl);
                af[mf][1] = lds_u32(ro + 1024 + kl);
                af[mf][2] = lds_u32(ro + kh);
                af[mf][3] = lds_u32(ro + 1024 + kh);
            }
            uint32_t bf[8][2];
#pragma unroll
            for (int nf = 0; nf < 8; nf++) {
                int r = wn * 64 + nf * 8 + g;
                uint32_t ro = sB + r * 128;
                uint32_t kx = (uint32_t)((r & 7) << 4);
                bf[nf][0] = lds_u32(ro + (((uint32_t)((k0 + tg) * 4)) ^ kx));
                bf[nf][1] = lds_u32(ro + (((uint32_t)((k0 + tg + 4) * 4)) ^ kx));
            }
#pragma unroll
            for (int mf = 0; mf < 4; mf++)
#pragma unroll
                for (int nf = 0; nf < 8; nf++)
                    mma_tf32(acc[mf][nf], af[mf], bf[nf]);
        }
    };

    // prologue: 2 chunks
    load_chunk(0);
    load_chunk(1);

    for (int it = 0; it < nk; it += 2) {
        asm volatile("cp.async.wait_group 0;" ::: "memory");
        __syncthreads();   // also orders reuse of buffers (it+2)&3, (it+3)&3
        if (it + 2 < nk) {
            load_chunk(it + 2);
            load_chunk(it + 3);
        }
        compute_chunk(it);
        compute_chunk(it + 1);
    }

    // ---- epilogue ----
#pragma unroll
    for (int mf = 0; mf < 4; mf++) {
#pragma unroll
        for (int half = 0; half < 2; half++) {
            int row = by * TM + wm * 64 + mf * 16 + g + half * 8;
            if (MODE == 2) {
                float* Arow = C + (size_t)row * (N / 2) + bx * (TN / 2) + wn * 32;
#pragma unroll
                for (int nf = 0; nf < 8; nf++) {
                    float gv = acc[mf][nf][half * 2 + 0];
                    float uv = acc[mf][nf][half * 2 + 1];
                    Arow[nf * 4 + tg] = tf32rnd(gv / (1.f + __expf(-gv)) * uv);
                }
            } else {
                float* Crow = C + (size_t)row * N + bx * TN + wn * 64;
                const float* Rrow = (MODE == 1)
                    ? (R + (size_t)row * N + bx * TN + wn * 64) : (const float*)0;
#pragma unroll
                for (int nf = 0; nf < 8; nf++) {
                    int col = nf * 8 + tg * 2;
                    float2 v = make_float2(acc[mf][nf][half * 2 + 0],
                                           acc[mf][nf][half * 2 + 1]);
                    if (MODE == 1) {
                        v.x += Rrow[col];
                        v.y += Rrow[col + 1];
                    }
                    *(float2*)(Crow + col) = v;
                }
            }
        }
    }
}

// ---------------- weight transpose + tf32 round (float4 both sides, 64x64 tile) -------
// INTERLEAVE=0: out[n][k] = rnd(in[k][n]).
// INTERLEAVE=1 (gate_up): out row 2j = col j (gate), row 2j+1 = col j+INTD (up).
template <int INTERLEAVE>
__global__ void transpose_round_kernel(const float* __restrict__ in,
                                       float* __restrict__ out, int K, int N) {
    __shared__ float tt[64][65];
    int n0 = blockIdx.x * 64, k0 = blockIdx.y * 64;
    int tx = threadIdx.x, ty = threadIdx.y;   // 16 x 16
#pragma unroll
    for (int r = 0; r < 4; r++) {
        int k = k0 + ty + r * 16;
        float4 v = *(const float4*)(in + (size_t)k * N + n0 + 4 * tx);
        tt[4 * tx + 0][ty + r * 16] = v.x;
        tt[4 * tx + 1][ty + r * 16] = v.y;
        tt[4 * tx + 2][ty + r * 16] = v.z;
        tt[4 * tx + 3][ty + r * 16] = v.w;
    }
    __syncthreads();
#pragma unroll
    for (int r = 0; r < 4; r++) {
        int nl = ty + r * 16;
        int n = n0 + nl;
        size_t rowI;
        if (INTERLEAVE)
            rowI = (n < INTD) ? (size_t)(2 * n) : (size_t)(2 * (n - INTD) + 1);
        else
            rowI = (size_t)n;
        float4 w = make_float4(tf32rnd(tt[nl][4 * tx + 0]), tf32rnd(tt[nl][4 * tx + 1]),
                               tf32rnd(tt[nl][4 * tx + 2]), tf32rnd(tt[nl][4 * tx + 3]));
        *(float4*)(out + rowI * K + k0 + 4 * tx) = w;
    }
}

// ---------------- RMSNorm (output tf32-rounded) ----------------
__global__ void rmsnorm_kernel(const float* __restrict__ x, const float* __restrict__ w,
                               float* __restrict__ out) {
    int row = blockIdx.x;
    const float* xr = x + (size_t)row * HIDD;
    __shared__ float red[256];
    float4 vals[2];
    float s = 0.f;
#pragma unroll
    for (int i = 0; i < 2; i++) {
        float4 v = *(const float4*)(xr + (threadIdx.x + i * 256) * 4);
        vals[i] = v;
        s += v.x * v.x + v.y * v.y + v.z * v.z + v.w * v.w;
    }
    red[threadIdx.x] = s;
    __syncthreads();
    for (int off = 128; off > 0; off >>= 1) {
        if (threadIdx.x < off) red[threadIdx.x] += red[threadIdx.x + off];
        __syncthreads();
    }
    float inv = rsqrtf(red[0] / (float)HIDD + 1e-6f);
#pragma unroll
    for (int i = 0; i < 2; i++) {
        int c = (threadIdx.x + i * 256) * 4;
        float4 v = vals[i];
        float4 wv = *(const float4*)(w + c);
        float4 o = make_float4(tf32rnd(v.x * inv * wv.x), tf32rnd(v.y * inv * wv.y),
                               tf32rnd(v.z * inv * wv.z), tf32rnd(v.w * inv * wv.w));
        *(float4*)(out + (size_t)row * HIDD + c) = o;
    }
}

// ---------------- RoPE ----------------
__global__ void rope_kernel(float* __restrict__ qkv, const int* __restrict__ pos) {
    __shared__ float cs[64], sn[64];
    int tok = blockIdx.x;
    int p = pos[tok % SQ];
    if (threadIdx.x < 64) {
        double freq = exp(-(double)threadIdx.x * (9.210340371976184 / 64.0));
        float ang = (float)((double)p * freq);
        float s, c;
        sincosf(ang, &s, &c);
        cs[threadIdx.x] = c;
        sn[threadIdx.x] = s;
    }
    __syncthreads();
    for (int item = threadIdx.x; item < (NH + NKV) * 64; item += blockDim.x) {
        int head = item >> 6;
        int d = item & 63;
        float c = cs[d], s = sn[d];
        float* base = qkv + (size_t)tok * QKVD + head * HDIM;
        float t1 = base[d];
        float t2 = base[d + 64];
        base[d]      = t1 * c - t2 * s;
        base[d + 64] = t2 * c + t1 * s;
    }
}

// ---------------- Tensor-core flash attention (tf32 mma, causal, GQA) ----------------
#define QP 132
#define VP 136
#define PP 68
#define ATTN_SMEM ((128 * QP + 64 * QP + 64 * VP + 128 * PP) * 4)

__global__ __launch_bounds__(256, 1) void attn_mma_kernel(const float* __restrict__ qkv,
                                                          float* __restrict__ attn_out) {
    extern __shared__ float smem[];
    float* Qs = smem;                    // 128 x QP
    float* Ks = Qs + 128 * QP;           // 64 x QP
    float* Vs = Ks + 64 * QP;            // 64 x VP
    float* Ps = Vs + 64 * VP;            // 128 x PP

    const int qt = (gridDim.x - 1) - blockIdx.x;
    const int h = blockIdx.y, b = blockIdx.z;
    const int kvh = h / (NH / NKV);
    const int tid = threadIdx.x, w = tid >> 5, lane = tid & 31;
    const int g = lane >> 2, tg = lane & 3;
    const int tokQ0 = b * SQ + qt * 128;

    const uint32_t sQ = smem_u32(Qs), sK = smem_u32(Ks), sV = smem_u32(Vs),
                   sP = smem_u32(Ps);

    for (int i = tid; i < 128 * 32; i += 256) {
        int r = i >> 5, c4 = (i & 31) * 4;
        float4 v = *(const float4*)(qkv + (size_t)(tokQ0 + r) * QKVD + h * HDIM + c4);
        v.x = tf32rnd(v.x); v.y = tf32rnd(v.y); v.z = tf32rnd(v.z); v.w = tf32rnd(v.w);
        *(float4*)(Qs + r * QP + c4) = v;
    }

    float o[16][4];
#pragma unroll
    for (int nf = 0; nf < 16; nf++)
#pragma unroll
        for (int z = 0; z < 4; z++) o[nf][z] = 0.f;
    float m0 = -1e30f, m1 = -1e30f, l0 = 0.f, l1 = 0.f;
    const float scale = 0.08838834764831845f;

    const int row0 = qt * 128 + w * 16 + g;
    const int ntile = 2 * qt + 2;

    for (int kt = 0; kt < ntile; kt++) {
        __syncthreads();
        {
            int tokK0 = b * SQ + kt * 64;
            for (int i = tid; i < 64 * 32; i += 256) {
                int r = i >> 5, c4 = (i & 31) * 4;
                const float* base = qkv + (size_t)(tokK0 + r) * QKVD;
                float4 kv = *(const float4*)(base + NH * HDIM + kvh * HDIM + c4);
                float4 vv = *(const float4*)(base + (NH + NKV) * HDIM + kvh * HDIM + c4);
                kv.x = tf32rnd(kv.x); kv.y = tf32rnd(kv.y);
                kv.z = tf32rnd(kv.z); kv.w = tf32rnd(kv.w);
                vv.x = tf32rnd(vv.x); vv.y = tf32rnd(vv.y);
                vv.z = tf32rnd(vv.z); vv.w = tf32rnd(vv.w);
                *(float4*)(Ks + r * QP + c4) = kv;
                *(float4*)(Vs + r * VP + c4) = vv;
            }
        }
        __syncthreads();

        if (kt * 64 > qt * 128 + w * 16 + 15) continue;

        float s[8][4];
#pragma unroll
        for (int nf = 0; nf < 8; nf++)
#pragma unroll
            for (int z = 0; z < 4; z++) s[nf][z] = 0.f;

        const uint32_t qrow = sQ + (uint32_t)((w * 16 + g) * QP) * 4;
#pragma unroll 4
        for (int ks = 0; ks < 16; ks++) {
            uint32_t ko = (uint32_t)(ks * 8 + tg) * 4;
            uint32_t a[4];
            a[0] = lds_u32(qrow + ko);
            a[1] = lds_u32(qrow + (uint32_t)(8 * QP) * 4 + ko);
            a[2] = lds_u32(qrow + ko + 16);
            a[3] = lds_u32(qrow + (uint32_t)(8 * QP) * 4 + ko + 16);
            uint32_t bq[8][2];
#pragma unroll
            for (int nf = 0; nf < 8; nf++) {
                uint32_t krow = sK + (uint32_t)((nf * 8 + g) * QP) * 4;
                bq[nf][0] = lds_u32(krow + ko);
                bq[nf][1] = lds_u32(krow + ko + 16);
            }
#pragma unroll
            for (int nf = 0; nf < 8; nf++)
                mma_tf32(s[nf], a, bq[nf]);
        }

        const bool domask = (kt >= 2 * qt);
        float mx0 = -1e30f, mx1 = -1e30f;
#pragma unroll
        for (int nf = 0; nf < 8; nf++) {
#pragma unroll
            for (int z = 0; z < 4; z++) {
                float v = s[nf][z] * scale;
                if (domask) {
                    int col = kt * 64 + nf * 8 + 2 * tg + (z & 1);
                    int row = (z < 2) ? row0 : row0 + 8;
                    if (col > row) v = -1e30f;
                }
                s[nf][z] = v;
            }
            mx0 = fmaxf(mx0, fmaxf(s[nf][0], s[nf][1]));
            mx1 = fmaxf(mx1, fmaxf(s[nf][2], s[nf][3]));
        }
        mx0 = fmaxf(mx0, __shfl_xor_sync(0xffffffffu, mx0, 1));
        mx0 = fmaxf(mx0, __shfl_xor_sync(0xffffffffu, mx0, 2));
        mx1 = fmaxf(mx1, __shfl_xor_sync(0xffffffffu, mx1, 1));
        mx1 = fmaxf(mx1, __shfl_xor_sync(0xffffffffu, mx1, 2));
        float mn0 = fmaxf(m0, mx0), mn1 = fmaxf(m1, mx1);
        float c0 = __expf(m0 - mn0), c1 = __expf(m1 - mn1);
        float sum0 = 0.f, sum1 = 0.f;
        float* prow0 = Ps + (w * 16 + g) * PP + 2 * tg;
        float* prow1 = prow0 + 8 * PP;
#pragma unroll
        for (int nf = 0; nf < 8; nf++) {
            float p0 = tf32rnd(__expf(s[nf][0] - mn0));
            float p1 = tf32rnd(__expf(s[nf][1] - mn0));
            float p2 = tf32rnd(__expf(s[nf][2] - mn1));
            float p3 = tf32rnd(__expf(s[nf][3] - mn1));
            sum0 += p0 + p1;
            sum1 += p2 + p3;
            *(float2*)(prow0 + nf * 8) = make_float2(p0, p1);
            *(float2*)(prow1 + nf * 8) = make_float2(p2, p3);
        }
        sum0 += __shfl_xor_sync(0xffffffffu, sum0, 1);
        sum0 += __shfl_xor_sync(0xffffffffu, sum0, 2);
        sum1 += __shfl_xor_sync(0xffffffffu, sum1, 1);
        sum1 += __shfl_xor_sync(0xffffffffu, sum1, 2);
        l0 = l0 * c0 + sum0;
        l1 = l1 * c1 + sum1;
        m0 = mn0; m1 = mn1;
#pragma unroll
        for (int nf = 0; nf < 16; nf++) {
            o[nf][0] *= c0; o[nf][1] *= c0;
            o[nf][2] *= c1; o[nf][3] *= c1;
        }
        __syncwarp();

        const uint32_t prow = sP + (uint32_t)((w * 16 + g) * PP) * 4;
#pragma unroll 2
        for (int ks = 0; ks < 8; ks++) {
            uint32_t ko = (uint32_t)(ks * 8 + tg) * 4;
            uint32_t a[4];
            a[0] = lds_u32(prow + ko);
            a[1] = lds_u32(prow + (uint32_t)(8 * PP) * 4 + ko);
            a[2] = lds_u32(prow + ko + 16);
            a[3] = lds_u32(prow + (uint32_t)(8 * PP) * 4 + ko + 16);
            uint32_t v0 = sV + (uint32_t)((ks * 8 + tg) * VP + g) * 4;
            uint32_t v1 = sV + (uint32_t)((ks * 8 + tg + 4) * VP + g) * 4;
            uint32_t bv[16][2];
#pragma unroll
            for (int nf = 0; nf < 16; nf++) {
                bv[nf][0] = lds_u32(v0 + nf * 32);
                bv[nf][1] = lds_u32(v1 + nf * 32);
            }
#pragma unroll
            for (int nf = 0; nf < 16; nf++)
                mma_tf32(o[nf], a, bv[nf]);
        }
    }

    float inv0 = 1.f / l0, inv1 = 1.f / l1;
    float* orow0 = attn_out + (size_t)(tokQ0 + w * 16 + g) * HIDD + h * HDIM;
    float* orow1 = orow0 + (size_t)8 * HIDD;
#pragma unroll
    for (int nf = 0; nf < 16; nf++) {
        int col = nf * 8 + 2 * tg;
        *(float2*)(orow0 + col) = make_float2(tf32rnd(o[nf][0] * inv0),
                                              tf32rnd(o[nf][1] * inv0));
        *(float2*)(orow1 + col) = make_float2(tf32rnd(o[nf][2] * inv1),
                                              tf32rnd(o[nf][3] * inv1));
    }
}

extern "C" void kernel_launch(void* const* d_in, const int* in_sizes, int n_in,
                              void* d_out, int out_size) {
    const float* x    = (const float*)d_in[0];
    const float* ln1  = (const float*)d_in[1];
    const float* wqkv = (const float*)d_in[2];
    const float* wo   = (const float*)d_in[3];
    const float* ln2  = (const float*)d_in[4];
    const float* wgu  = (const float*)d_in[5];
    const float* wdn  = (const float*)d_in[6];
    const int*   pos  = (const int*)d_in[7];
    float* out = (float*)d_out;

    void *xn, *qkv, *attn, *h1, *h2, *act;
    void *wqkvT, *woT, *wguT, *wdnT;
    cudaGetSymbolAddress(&xn, g_xn);
    cudaGetSymbolAddress(&qkv, g_qkv);
    cudaGetSymbolAddress(&attn, g_attn);
    cudaGetSymbolAddress(&h1, g_h1);
    cudaGetSymbolAddress(&h2, g_h2);
    cudaGetSymbolAddress(&act, g_act);
    cudaGetSymbolAddress(&wqkvT, g_wqkvT);
    cudaGetSymbolAddress(&woT, g_woT);
    cudaGetSymbolAddress(&wguT, g_wguT);
    cudaGetSymbolAddress(&wdnT, g_wdnT);

    cudaFuncSetAttribute(attn_mma_kernel, cudaFuncAttributeMaxDynamicSharedMemorySize, ATTN_SMEM);
    cudaFuncSetAttribute(tc_gemm<0>, cudaFuncAttributeMaxDynamicSharedMemorySize, GEMM_SMEM_TC);
    cudaFuncSetAttribute(tc_gemm<1>, cudaFuncAttributeMaxDynamicSharedMemorySize, GEMM_SMEM_TC);
    cudaFuncSetAttribute(tc_gemm<2>, cudaFuncAttributeMaxDynamicSharedMemorySize, GEMM_SMEM_TC);

    // 0. weight transpose + tf32 rounding (gate_up interleaved), 64x64 float4 tiles
    {
        dim3 bb(16, 16);
        transpose_round_kernel<0><<<dim3(QKVD / 64, HIDD / 64), bb>>>(wqkv, (float*)wqkvT, HIDD, QKVD);
        transpose_round_kernel<0><<<dim3(HIDD / 64, HIDD / 64), bb>>>(wo, (float*)woT, HIDD, HIDD);
        transpose_round_kernel<1><<<dim3(2 * INTD / 64, HIDD / 64), bb>>>(wgu, (float*)wguT, HIDD, 2 * INTD);
        transpose_round_kernel<0><<<dim3(HIDD / 64, INTD / 64), bb>>>(wdn, (float*)wdnT, INTD, HIDD);
    }
    // 1. h = rmsnorm(x, ln1)
    rmsnorm_kernel<<<NTOK, 256>>>(x, ln1, (float*)xn);
    // 2. qkv = h @ wqkv
    tc_gemm<0><<<dim3(NTOK / TM, QKVD / TN), 256, GEMM_SMEM_TC>>>(
        (const float*)xn, (const float*)wqkvT, nullptr, (float*)qkv, QKVD, HIDD);
    // 3. RoPE
    rope_kernel<<<NTOK, 256>>>((float*)qkv, pos);
    // 4. attention
    {
        dim3 g(SQ / 128, NH, BATCH);
        attn_mma_kernel<<<g, 256, ATTN_SMEM>>>((const float*)qkv, (float*)attn);
    }
    // 5. h1 = x + attn @ wo
    tc_gemm<1><<<dim3(NTOK / TM, HIDD / TN), 256, GEMM_SMEM_TC>>>(
        (const float*)attn, (const float*)woT, x, (float*)h1, HIDD, HIDD);
    // 6. h2 = rmsnorm(h1, ln2)
    rmsnorm_kernel<<<NTOK, 256>>>((const float*)h1, ln2, (float*)h2);
    // 7+8. act = silu(h2 @ w_gate) * (h2 @ w_up)  — fused epilogue
    tc_gemm<2><<<dim3(NTOK / TM, 2 * INTD / TN), 256, GEMM_SMEM_TC>>>(
        (const float*)h2, (const float*)wguT, nullptr, (float*)act, 2 * INTD, HIDD);
    // 9. out = h1 + act @ w_down
    tc_gemm<1><<<dim3(NTOK / TM, HIDD / TN), 256, GEMM_SMEM_TC>>>(
        (const float*)act, (const float*)wdnT, (const float*)h1, out, HIDD, INTD);
}

// round 11
// speedup vs baseline: 3.2410x; 1.7403x over previous
#include <cuda_runtime.h>
#include <cuda_fp16.h>
#include <math.h>
#include <stdint.h>

#define NTOK 4096
#define SQ   1024
#define BATCH 4
#define HIDD 2048
#define NH   16
#define NKV  4
#define HDIM 128
#define QKVD 3072   // (16+2*4)*128
#define INTD 8192

// ---------------- scratch (static device memory; no allocations) ----------------
__device__ __half g_xn  [(size_t)NTOK * HIDD];
__device__ float  g_qkv [(size_t)NTOK * QKVD];
__device__ __half g_attn[(size_t)NTOK * HIDD];
__device__ float  g_h1  [(size_t)NTOK * HIDD];
__device__ __half g_h2  [(size_t)NTOK * HIDD];
__device__ __half g_act [(size_t)NTOK * INTD];
// transposed + fp16 weights [N, K] K-major
__device__ __half g_wqkvT [(size_t)QKVD * HIDD];
__device__ __half g_woT   [(size_t)HIDD * HIDD];
__device__ __half g_wguT  [(size_t)2 * INTD * HIDD];  // interleaved: row 2j=gate_j, 2j+1=up_j
__device__ __half g_wdnT  [(size_t)HIDD * INTD];

// ---------------- helpers ----------------
__device__ __forceinline__ float tf32rnd(float x) {
    uint32_t u;
    asm("cvt.rna.tf32.f32 %0, %1;" : "=r"(u) : "f"(x));
    return __uint_as_float(u);
}

__device__ __forceinline__ uint32_t smem_u32(const void* p) {
    uint32_t a;
    asm("{ .reg .u64 t; cvta.to.shared.u64 t, %1; cvt.u32.u64 %0, t; }"
        : "=r"(a) : "l"(p));
    return a;
}

__device__ __forceinline__ uint32_t lds_u32(uint32_t a) {
    uint32_t v;
    asm volatile("ld.shared.b32 %0, [%1];" : "=r"(v) : "r"(a));
    return v;
}

#define SWZ128(o) ((o) ^ (((o) >> 3) & 0x70))

#define CP_ASYNC16(dst, src) \
    asm volatile("cp.async.cg.shared.global [%0], [%1], 16;" :: "r"(dst), "l"(src) : "memory")
#define CP_COMMIT() asm volatile("cp.async.commit_group;" ::: "memory")

__device__ __forceinline__ void mma_tf32(float* c, const uint32_t* a, const uint32_t* b) {
    asm volatile(
        "mma.sync.aligned.m16n8k8.row.col.f32.tf32.tf32.f32 "
        "{%0,%1,%2,%3}, {%4,%5,%6,%7}, {%8,%9}, {%0,%1,%2,%3};\n"
        : "+f"(c[0]), "+f"(c[1]), "+f"(c[2]), "+f"(c[3])
        : "r"(a[0]), "r"(a[1]), "r"(a[2]), "r"(a[3]), "r"(b[0]), "r"(b[1]));
}

__device__ __forceinline__ void mma_f16(float* c, const uint32_t* a, const uint32_t* b) {
    asm volatile(
        "mma.sync.aligned.m16n8k16.row.col.f32.f16.f16.f32 "
        "{%0,%1,%2,%3}, {%4,%5,%6,%7}, {%8,%9}, {%0,%1,%2,%3};\n"
        : "+f"(c[0]), "+f"(c[1]), "+f"(c[2]), "+f"(c[3])
        : "r"(a[0]), "r"(a[1]), "r"(a[2]), "r"(a[3]), "r"(b[0]), "r"(b[1]));
}

// ---------------- HMMA fp16 GEMM: tile 256(M)x128(N), KC=64 halves, 4-stage, 2/sync ----
// MODE: 0 = plain fp32 out, 1 = +fp32 residual, 2 = silu-fused fp16 out (interleaved)
#define TM 256
#define TN 128
#define KC 64
#define NSTG 4
#define ASZ (TM * KC * 2)     // 32768 B (rows of 128 B)
#define BSZ (TN * KC * 2)     // 16384 B
#define STGB (ASZ + BSZ)      // 49152 B
#define GEMM_SMEM_TC (NSTG * STGB)   // 196608 B

template <int MODE>
__global__ __launch_bounds__(256, 1) void tc_gemm(const __half* __restrict__ A,
                                                  const __half* __restrict__ Bt,
                                                  const float* __restrict__ R,
                                                  void* __restrict__ Cv,
                                                  int N, int K) {
    extern __shared__ char smc[];
    const uint32_t sb = smem_u32(smc);
    const int tid = threadIdx.x;
    const int lane = tid & 31, w = tid >> 5;
    const int wm = w >> 1, wn = w & 1;
    const int g = lane >> 2, tg = lane & 3;
    const int by = blockIdx.x, bx = blockIdx.y;

    const __half* Ab = A + (size_t)(by * TM) * K;
    const __half* Bb = Bt + (size_t)(bx * TN) * K;
    const int nk = K / KC;   // even for all our shapes

    const int lrow = tid >> 3;
    const int lseg = tid & 7;

    float acc[4][8][4];
#pragma unroll
    for (int i = 0; i < 4; i++)
#pragma unroll
        for (int j = 0; j < 8; j++)
#pragma unroll
            for (int z = 0; z < 4; z++) acc[i][j][z] = 0.f;

    auto load_chunk = [&](int j) {
        uint32_t st = sb + (j & 3) * STGB;
#pragma unroll
        for (int i = 0; i < 8; i++) {
            int r = i * 32 + lrow;
            uint32_t off = (uint32_t)(r * 128 + lseg * 16);
            CP_ASYNC16(st + SWZ128(off), Ab + (size_t)r * K + j * KC + lseg * 8);
        }
        uint32_t stB = st + ASZ;
#pragma unroll
        for (int i = 0; i < 4; i++) {
            int r = i * 32 + lrow;
            uint32_t off = (uint32_t)(r * 128 + lseg * 16);
            CP_ASYNC16(stB + SWZ128(off), Bb + (size_t)r * K + j * KC + lseg * 8);
        }
        CP_COMMIT();
    };

    auto compute_chunk = [&](int it) {
        const uint32_t sA = sb + (it & 3) * STGB;
        const uint32_t sB = sA + ASZ;
#pragma unroll
        for (int kk = 0; kk < 4; kk++) {      // each kk = 16 halves of k
            const int k0 = kk * 8;            // word-pair base within 32-word row
            uint32_t af[4][4];
#pragma unroll
            for (int mf = 0; mf < 4; mf++) {
                int r0 = wm * 64 + mf * 16 + g;
                uint32_t ro = sA + r0 * 128;
                uint32_t kx = (uint32_t)((r0 & 7) << 4);
                uint32_t kl = ((uint32_t)((k0 + tg) * 4)) ^ kx;
                uint32_t kh = ((uint32_t)((k0 + tg + 4) * 4)) ^ kx;
                af[mf][0] = lds_u32(ro + kl);          // rows g,   k 2tg..
                af[mf][1] = lds_u32(ro + 1024 + kl);   // rows g+8
                af[mf][2] = lds_u32(ro + kh);          // k +8
                af[mf][3] = lds_u32(ro + 1024 + kh);
            }
            uint32_t bf[8][2];
#pragma unroll
            for (int nf = 0; nf < 8; nf++) {
                int r = wn * 64 + nf * 8 + g;
                uint32_t ro = sB + r * 128;
                uint32_t kx = (uint32_t)((r & 7) << 4);
                bf[nf][0] = lds_u32(ro + (((uint32_t)((k0 + tg) * 4)) ^ kx));
                bf[nf][1] = lds_u32(ro + (((uint32_t)((k0 + tg + 4) * 4)) ^ kx));
            }
#pragma unroll
            for (int mf = 0; mf < 4; mf++)
#pragma unroll
                for (int nf = 0; nf < 8; nf++)
                    mma_f16(acc[mf][nf], af[mf], bf[nf]);
        }
    };

    load_chunk(0);
    load_chunk(1);

    for (int it = 0; it < nk; it += 2) {
        asm volatile("cp.async.wait_group 0;" ::: "memory");
        __syncthreads();
        if (it + 2 < nk) {
            load_chunk(it + 2);
            load_chunk(it + 3);
        }
        compute_chunk(it);
        compute_chunk(it + 1);
    }

    // ---- epilogue ----
#pragma unroll
    for (int mf = 0; mf < 4; mf++) {
#pragma unroll
        for (int half = 0; half < 2; half++) {
            int row = by * TM + wm * 64 + mf * 16 + g + half * 8;
            if (MODE == 2) {
                __half* Arow = (__half*)Cv + (size_t)row * (N / 2) + bx * (TN / 2) + wn * 32;
#pragma unroll
                for (int nf = 0; nf < 8; nf++) {
                    float gv = acc[mf][nf][half * 2 + 0];
                    float uv = acc[mf][nf][half * 2 + 1];
                    Arow[nf * 4 + tg] = __float2half_rn(gv / (1.f + __expf(-gv)) * uv);
                }
            } else {
                float* Crow = (float*)Cv + (size_t)row * N + bx * TN + wn * 64;
                const float* Rrow = (MODE == 1)
                    ? (R + (size_t)row * N + bx * TN + wn * 64) : (const float*)0;
#pragma unroll
                for (int nf = 0; nf < 8; nf++) {
                    int col = nf * 8 + tg * 2;
                    float2 v = make_float2(acc[mf][nf][half * 2 + 0],
                                           acc[mf][nf][half * 2 + 1]);
                    if (MODE == 1) {
                        v.x += Rrow[col];
                        v.y += Rrow[col + 1];
                    }
                    *(float2*)(Crow + col) = v;
                }
            }
        }
    }
}

// ---------------- weight transpose + fp16 convert (float4 in, 64x64 tile) -------------
// INTERLEAVE=0: out[n][k] = h(in[k][n]). 1: gate_up interleave rows.
template <int INTERLEAVE>
__global__ void transpose_round_kernel(const float* __restrict__ in,
                                       __half* __restrict__ out, int K, int N) {
    __shared__ float tt[64][65];
    int n0 = blockIdx.x * 64, k0 = blockIdx.y * 64;
    int tx = threadIdx.x, ty = threadIdx.y;   // 16 x 16
#pragma unroll
    for (int r = 0; r < 4; r++) {
        int k = k0 + ty + r * 16;
        float4 v = *(const float4*)(in + (size_t)k * N + n0 + 4 * tx);
        tt[4 * tx + 0][ty + r * 16] = v.x;
        tt[4 * tx + 1][ty + r * 16] = v.y;
        tt[4 * tx + 2][ty + r * 16] = v.z;
        tt[4 * tx + 3][ty + r * 16] = v.w;
    }
    __syncthreads();
#pragma unroll
    for (int r = 0; r < 4; r++) {
        int nl = ty + r * 16;
        int n = n0 + nl;
        size_t rowI;
        if (INTERLEAVE)
            rowI = (n < INTD) ? (size_t)(2 * n) : (size_t)(2 * (n - INTD) + 1);
        else
            rowI = (size_t)n;
        __half2 h01 = __floats2half2_rn(tt[nl][4 * tx + 0], tt[nl][4 * tx + 1]);
        __half2 h23 = __floats2half2_rn(tt[nl][4 * tx + 2], tt[nl][4 * tx + 3]);
        __half2* dst = (__half2*)(out + rowI * K + k0 + 4 * tx);
        dst[0] = h01;
        dst[1] = h23;
    }
}

// ---------------- RMSNorm (fp16 output; feeds GEMM A) ----------------
__global__ void rmsnorm_kernel(const float* __restrict__ x, const float* __restrict__ w,
                               __half* __restrict__ out) {
    int row = blockIdx.x;
    const float* xr = x + (size_t)row * HIDD;
    __shared__ float red[256];
    float4 vals[2];
    float s = 0.f;
#pragma unroll
    for (int i = 0; i < 2; i++) {
        float4 v = *(const float4*)(xr + (threadIdx.x + i * 256) * 4);
        vals[i] = v;
        s += v.x * v.x + v.y * v.y + v.z * v.z + v.w * v.w;
    }
    red[threadIdx.x] = s;
    __syncthreads();
    for (int off = 128; off > 0; off >>= 1) {
        if (threadIdx.x < off) red[threadIdx.x] += red[threadIdx.x + off];
        __syncthreads();
    }
    float inv = rsqrtf(red[0] / (float)HIDD + 1e-6f);
#pragma unroll
    for (int i = 0; i < 2; i++) {
        int c = (threadIdx.x + i * 256) * 4;
        float4 v = vals[i];
        float4 wv = *(const float4*)(w + c);
        __half2 h01 = __floats2half2_rn(v.x * inv * wv.x, v.y * inv * wv.y);
        __half2 h23 = __floats2half2_rn(v.z * inv * wv.z, v.w * inv * wv.w);
        __half2* dst = (__half2*)(out + (size_t)row * HIDD + c);
        dst[0] = h01;
        dst[1] = h23;
    }
}

// ---------------- RoPE ----------------
__global__ void rope_kernel(float* __restrict__ qkv, const int* __restrict__ pos) {
    __shared__ float cs[64], sn[64];
    int tok = blockIdx.x;
    int p = pos[tok % SQ];
    if (threadIdx.x < 64) {
        double freq = exp(-(double)threadIdx.x * (9.210340371976184 / 64.0));
        float ang = (float)((double)p * freq);
        float s, c;
        sincosf(ang, &s, &c);
        cs[threadIdx.x] = c;
        sn[threadIdx.x] = s;
    }
    __syncthreads();
    for (int item = threadIdx.x; item < (NH + NKV) * 64; item += blockDim.x) {
        int head = item >> 6;
        int d = item & 63;
        float c = cs[d], s = sn[d];
        float* base = qkv + (size_t)tok * QKVD + head * HDIM;
        float t1 = base[d];
        float t2 = base[d + 64];
        base[d]      = t1 * c - t2 * s;
        base[d + 64] = t2 * c + t1 * s;
    }
}

// ---------------- Tensor-core flash attention (tf32 mma, causal, GQA; fp16 out) -------
#define QP 132
#define VP 136
#define PP 68
#define ATTN_SMEM ((128 * QP + 64 * QP + 64 * VP + 128 * PP) * 4)

__global__ __launch_bounds__(256, 1) void attn_mma_kernel(const float* __restrict__ qkv,
                                                          __half* __restrict__ attn_out) {
    extern __shared__ float smem[];
    float* Qs = smem;                    // 128 x QP
    float* Ks = Qs + 128 * QP;           // 64 x QP
    float* Vs = Ks + 64 * QP;            // 64 x VP
    float* Ps = Vs + 64 * VP;            // 128 x PP

    const int qt = (gridDim.x - 1) - blockIdx.x;
    const int h = blockIdx.y, b = blockIdx.z;
    const int kvh = h / (NH / NKV);
    const int tid = threadIdx.x, w = tid >> 5, lane = tid & 31;
    const int g = lane >> 2, tg = lane & 3;
    const int tokQ0 = b * SQ + qt * 128;

    const uint32_t sQ = smem_u32(Qs), sK = smem_u32(Ks), sV = smem_u32(Vs),
                   sP = smem_u32(Ps);

    for (int i = tid; i < 128 * 32; i += 256) {
        int r = i >> 5, c4 = (i & 31) * 4;
        float4 v = *(const float4*)(qkv + (size_t)(tokQ0 + r) * QKVD + h * HDIM + c4);
        v.x = tf32rnd(v.x); v.y = tf32rnd(v.y); v.z = tf32rnd(v.z); v.w = tf32rnd(v.w);
        *(float4*)(Qs + r * QP + c4) = v;
    }

    float o[16][4];
#pragma unroll
    for (int nf = 0; nf < 16; nf++)
#pragma unroll
        for (int z = 0; z < 4; z++) o[nf][z] = 0.f;
    float m0 = -1e30f, m1 = -1e30f, l0 = 0.f, l1 = 0.f;
    const float scale = 0.08838834764831845f;

    const int row0 = qt * 128 + w * 16 + g;
    const int ntile = 2 * qt + 2;

    for (int kt = 0; kt < ntile; kt++) {
        __syncthreads();
        {
            int tokK0 = b * SQ + kt * 64;
            for (int i = tid; i < 64 * 32; i += 256) {
                int r = i >> 5, c4 = (i & 31) * 4;
                const float* base = qkv + (size_t)(tokK0 + r) * QKVD;
                float4 kv = *(const float4*)(base + NH * HDIM + kvh * HDIM + c4);
                float4 vv = *(const float4*)(base + (NH + NKV) * HDIM + kvh * HDIM + c4);
                kv.x = tf32rnd(kv.x); kv.y = tf32rnd(kv.y);
                kv.z = tf32rnd(kv.z); kv.w = tf32rnd(kv.w);
                vv.x = tf32rnd(vv.x); vv.y = tf32rnd(vv.y);
                vv.z = tf32rnd(vv.z); vv.w = tf32rnd(vv.w);
                *(float4*)(Ks + r * QP + c4) = kv;
                *(float4*)(Vs + r * VP + c4) = vv;
            }
        }
        __syncthreads();

        if (kt * 64 > qt * 128 + w * 16 + 15) continue;

        float s[8][4];
#pragma unroll
        for (int nf = 0; nf < 8; nf++)
#pragma unroll
            for (int z = 0; z < 4; z++) s[nf][z] = 0.f;

        const uint32_t qrow = sQ + (uint32_t)((w * 16 + g) * QP) * 4;
#pragma unroll 4
        for (int ks = 0; ks < 16; ks++) {
            uint32_t ko = (uint32_t)(ks * 8 + tg) * 4;
            uint32_t a[4];
            a[0] = lds_u32(qrow + ko);
            a[1] = lds_u32(qrow + (uint32_t)(8 * QP) * 4 + ko);
            a[2] = lds_u32(qrow + ko + 16);
            a[3] = lds_u32(qrow + (uint32_t)(8 * QP) * 4 + ko + 16);
            uint32_t bq[8][2];
#pragma unroll
            for (int nf = 0; nf < 8; nf++) {
                uint32_t krow = sK + (uint32_t)((nf * 8 + g) * QP) * 4;
                bq[nf][0] = lds_u32(krow + ko);
                bq[nf][1] = lds_u32(krow + ko + 16);
            }
#pragma unroll
            for (int nf = 0; nf < 8; nf++)
                mma_tf32(s[nf], a, bq[nf]);
        }

        const bool domask = (kt >= 2 * qt);
        float mx0 = -1e30f, mx1 = -1e30f;
#pragma unroll
        for (int nf = 0; nf < 8; nf++) {
#pragma unroll
            for (int z = 0; z < 4; z++) {
                float v = s[nf][z] * scale;
                if (domask) {
                    int col = kt * 64 + nf * 8 + 2 * tg + (z & 1);
                    int row = (z < 2) ? row0 : row0 + 8;
                    if (col > row) v = -1e30f;
                }
                s[nf][z] = v;
            }
            mx0 = fmaxf(mx0, fmaxf(s[nf][0], s[nf][1]));
            mx1 = fmaxf(mx1, fmaxf(s[nf][2], s[nf][3]));
        }
        mx0 = fmaxf(mx0, __shfl_xor_sync(0xffffffffu, mx0, 1));
        mx0 = fmaxf(mx0, __shfl_xor_sync(0xffffffffu, mx0, 2));
        mx1 = fmaxf(mx1, __shfl_xor_sync(0xffffffffu, mx1, 1));
        mx1 = fmaxf(mx1, __shfl_xor_sync(0xffffffffu, mx1, 2));
        float mn0 = fmaxf(m0, mx0), mn1 = fmaxf(m1, mx1);
        float c0 = __expf(m0 - mn0), c1 = __expf(m1 - mn1);
        float sum0 = 0.f, sum1 = 0.f;
        float* prow0 = Ps + (w * 16 + g) * PP + 2 * tg;
        float* prow1 = prow0 + 8 * PP;
#pragma unroll
        for (int nf = 0; nf < 8; nf++) {
            float p0 = tf32rnd(__expf(s[nf][0] - mn0));
            float p1 = tf32rnd(__expf(s[nf][1] - mn0));
            float p2 = tf32rnd(__expf(s[nf][2] - mn1));
            float p3 = tf32rnd(__expf(s[nf][3] - mn1));
            sum0 += p0 + p1;
            sum1 += p2 + p3;
            *(float2*)(prow0 + nf * 8) = make_float2(p0, p1);
            *(float2*)(prow1 + nf * 8) = make_float2(p2, p3);
        }
        sum0 += __shfl_xor_sync(0xffffffffu, sum0, 1);
        sum0 += __shfl_xor_sync(0xffffffffu, sum0, 2);
        sum1 += __shfl_xor_sync(0xffffffffu, sum1, 1);
        sum1 += __shfl_xor_sync(0xffffffffu, sum1, 2);
        l0 = l0 * c0 + sum0;
        l1 = l1 * c1 + sum1;
        m0 = mn0; m1 = mn1;
#pragma unroll
        for (int nf = 0; nf < 16; nf++) {
            o[nf][0] *= c0; o[nf][1] *= c0;
            o[nf][2] *= c1; o[nf][3] *= c1;
        }
        __syncwarp();

        const uint32_t prow = sP + (uint32_t)((w * 16 + g) * PP) * 4;
#pragma unroll 2
        for (int ks = 0; ks < 8; ks++) {
            uint32_t ko = (uint32_t)(ks * 8 + tg) * 4;
            uint32_t a[4];
            a[0] = lds_u32(prow + ko);
            a[1] = lds_u32(prow + (uint32_t)(8 * PP) * 4 + ko);
            a[2] = lds_u32(prow + ko + 16);
            a[3] = lds_u32(prow + (uint32_t)(8 * PP) * 4 + ko + 16);
            uint32_t v0 = sV + (uint32_t)((ks * 8 + tg) * VP + g) * 4;
            uint32_t v1 = sV + (uint32_t)((ks * 8 + tg + 4) * VP + g) * 4;
            uint32_t bv[16][2];
#pragma unroll
            for (int nf = 0; nf < 16; nf++) {
                bv[nf][0] = lds_u32(v0 + nf * 32);
                bv[nf][1] = lds_u32(v1 + nf * 32);
            }
#pragma unroll
            for (int nf = 0; nf < 16; nf++)
                mma_tf32(o[nf], a, bv[nf]);
        }
    }

    float inv0 = 1.f / l0, inv1 = 1.f / l1;
    __half* orow0 = attn_out + (size_t)(tokQ0 + w * 16 + g) * HIDD + h * HDIM;
    __half* orow1 = orow0 + (size_t)8 * HIDD;
#pragma unroll
    for (int nf = 0; nf < 16; nf++) {
        int col = nf * 8 + 2 * tg;
        *(__half2*)(orow0 + col) = __floats2half2_rn(o[nf][0] * inv0, o[nf][1] * inv0);
        *(__half2*)(orow1 + col) = __floats2half2_rn(o[nf][2] * inv1, o[nf][3] * inv1);
    }
}

extern "C" void kernel_launch(void* const* d_in, const int* in_sizes, int n_in,
                              void* d_out, int out_size) {
    const float* x    = (const float*)d_in[0];
    const float* ln1  = (const float*)d_in[1];
    const float* wqkv = (const float*)d_in[2];
    const float* wo   = (const float*)d_in[3];
    const float* ln2  = (const float*)d_in[4];
    const float* wgu  = (const float*)d_in[5];
    const float* wdn  = (const float*)d_in[6];
    const int*   pos  = (const int*)d_in[7];
    float* out = (float*)d_out;

    void *xn, *qkv, *attn, *h1, *h2, *act;
    void *wqkvT, *woT, *wguT, *wdnT;
    cudaGetSymbolAddress(&xn, g_xn);
    cudaGetSymbolAddress(&qkv, g_qkv);
    cudaGetSymbolAddress(&attn, g_attn);
    cudaGetSymbolAddress(&h1, g_h1);
    cudaGetSymbolAddress(&h2, g_h2);
    cudaGetSymbolAddress(&act, g_act);
    cudaGetSymbolAddress(&wqkvT, g_wqkvT);
    cudaGetSymbolAddress(&woT, g_woT);
    cudaGetSymbolAddress(&wguT, g_wguT);
    cudaGetSymbolAddress(&wdnT, g_wdnT);

    cudaFuncSetAttribute(attn_mma_kernel, cudaFuncAttributeMaxDynamicSharedMemorySize, ATTN_SMEM);
    cudaFuncSetAttribute(tc_gemm<0>, cudaFuncAttributeMaxDynamicSharedMemorySize, GEMM_SMEM_TC);
    cudaFuncSetAttribute(tc_gemm<1>, cudaFuncAttributeMaxDynamicSharedMemorySize, GEMM_SMEM_TC);
    cudaFuncSetAttribute(tc_gemm<2>, cudaFuncAttributeMaxDynamicSharedMemorySize, GEMM_SMEM_TC);

    // 0. weight transpose + fp16 convert (gate_up interleaved)
    {
        dim3 bb(16, 16);
        transpose_round_kernel<0><<<dim3(QKVD / 64, HIDD / 64), bb>>>(wqkv, (__half*)wqkvT, HIDD, QKVD);
        transpose_round_kernel<0><<<dim3(HIDD / 64, HIDD / 64), bb>>>(wo, (__half*)woT, HIDD, HIDD);
        transpose_round_kernel<1><<<dim3(2 * INTD / 64, HIDD / 64), bb>>>(wgu, (__half*)wguT, HIDD, 2 * INTD);
        transpose_round_kernel<0><<<dim3(HIDD / 64, INTD / 64), bb>>>(wdn, (__half*)wdnT, INTD, HIDD);
    }
    // 1. h = rmsnorm(x, ln1)  (fp16)
    rmsnorm_kernel<<<NTOK, 256>>>(x, ln1, (__half*)xn);
    // 2. qkv = h @ wqkv  (fp32 out)
    tc_gemm<0><<<dim3(NTOK / TM, QKVD / TN), 256, GEMM_SMEM_TC>>>(
        (const __half*)xn, (const __half*)wqkvT, nullptr, qkv, QKVD, HIDD);
    // 3. RoPE
    rope_kernel<<<NTOK, 256>>>((float*)qkv, pos);
    // 4. attention (tf32 mma, fp16 out)
    {
        dim3 g(SQ / 128, NH, BATCH);
        attn_mma_kernel<<<g, 256, ATTN_SMEM>>>((const float*)qkv, (__half*)attn);
    }
    // 5. h1 = x + attn @ wo  (fp32 out)
    tc_gemm<1><<<dim3(NTOK / TM, HIDD / TN), 256, GEMM_SMEM_TC>>>(
        (const __half*)attn, (const __half*)woT, x, h1, HIDD, HIDD);
    // 6. h2 = rmsnorm(h1, ln2)  (fp16)
    rmsnorm_kernel<<<NTOK, 256>>>((const float*)h1, ln2, (__half*)h2);
    // 7+8. act = silu(h2 @ w_gate) * (h2 @ w_up)  (fp16, fused epilogue)
    tc_gemm<2><<<dim3(NTOK / TM, 2 * INTD / TN), 256, GEMM_SMEM_TC>>>(
        (const __half*)h2, (const __half*)wguT, nullptr, act, 2 * INTD, HIDD);
    // 9. out = h1 + act @ w_down  (fp32 out)
    tc_gemm<1><<<dim3(NTOK / TM, HIDD / TN), 256, GEMM_SMEM_TC>>>(
        (const __half*)act, (const __half*)wdnT, (const float*)h1, out, HIDD, INTD);
}

// round 14
// speedup vs baseline: 3.4763x; 1.0726x over previous
#include <cuda_runtime.h>
#include <cuda_fp16.h>
#include <math.h>
#include <stdint.h>

#define NTOK 4096
#define SQ   1024
#define BATCH 4
#define HIDD 2048
#define NH   16
#define NKV  4
#define HDIM 128
#define QKVD 3072   // (16+2*4)*128
#define INTD 8192

// ---------------- scratch (static device memory; no allocations) ----------------
__device__ __half g_xn  [(size_t)NTOK * HIDD];
__device__ __half g_qkvh[(size_t)NTOK * QKVD];
__device__ __half g_attn[(size_t)NTOK * HIDD];
__device__ float  g_h1  [(size_t)NTOK * HIDD];
__device__ __half g_h2  [(size_t)NTOK * HIDD];
__device__ __half g_act [(size_t)NTOK * INTD];
// transposed fp16 weights [N, K] K-major
__device__ __half g_wqkvT [(size_t)QKVD * HIDD];
__device__ __half g_woT   [(size_t)HIDD * HIDD];
__device__ __half g_wguT  [(size_t)2 * INTD * HIDD];  // interleaved: row 2j=gate_j, 2j+1=up_j
__device__ __half g_wdnT  [(size_t)HIDD * INTD];

// ---------------- helpers ----------------
__device__ __forceinline__ uint32_t h2_as_u32(__half2 h) {
    uint32_t u;
    asm("mov.b32 %0, %1;" : "=r"(u) : "r"(*(unsigned int*)&h));
    return u;
}

__device__ __forceinline__ uint32_t smem_u32(const void* p) {
    uint32_t a;
    asm("{ .reg .u64 t; cvta.to.shared.u64 t, %1; cvt.u32.u64 %0, t; }"
        : "=r"(a) : "l"(p));
    return a;
}

__device__ __forceinline__ uint32_t lds_u32(uint32_t a) {
    uint32_t v;
    asm volatile("ld.shared.b32 %0, [%1];" : "=r"(v) : "r"(a));
    return v;
}

#define SWZ128(o) ((o) ^ (((o) >> 3) & 0x70))

#define CP_ASYNC16(dst, src) \
    asm volatile("cp.async.cg.shared.global [%0], [%1], 16;" :: "r"(dst), "l"(src) : "memory")
#define CP_COMMIT() asm volatile("cp.async.commit_group;" ::: "memory")

__device__ __forceinline__ void mma_f16(float* c, const uint32_t* a, const uint32_t* b) {
    asm volatile(
        "mma.sync.aligned.m16n8k16.row.col.f32.f16.f16.f32 "
        "{%0,%1,%2,%3}, {%4,%5,%6,%7}, {%8,%9}, {%0,%1,%2,%3};\n"
        : "+f"(c[0]), "+f"(c[1]), "+f"(c[2]), "+f"(c[3])
        : "r"(a[0]), "r"(a[1]), "r"(a[2]), "r"(a[3]), "r"(b[0]), "r"(b[1]));
}

// ---------------- HMMA fp16 GEMM: tile 256(M)x128(N), KC=64 halves, 4-stage, 2/sync ----
// MODE: 0 = fp32 out, 1 = +fp32 residual, 2 = silu-fused fp16 out, 3 = plain fp16 out
#define TM 256
#define TN 128
#define KC 64
#define NSTG 4
#define ASZ (TM * KC * 2)
#define BSZ (TN * KC * 2)
#define STGB (ASZ + BSZ)
#define GEMM_SMEM_TC (NSTG * STGB)   // 196608 B

template <int MODE>
__global__ __launch_bounds__(256, 1) void tc_gemm(const __half* __restrict__ A,
                                                  const __half* __restrict__ Bt,
                                                  const float* __restrict__ R,
                                                  void* __restrict__ Cv,
                                                  int N, int K) {
    extern __shared__ char smc[];
    const uint32_t sb = smem_u32(smc);
    const int tid = threadIdx.x;
    const int lane = tid & 31, w = tid >> 5;
    const int wm = w >> 1, wn = w & 1;
    const int g = lane >> 2, tg = lane & 3;
    const int by = blockIdx.x, bx = blockIdx.y;

    const __half* Ab = A + (size_t)(by * TM) * K;
    const __half* Bb = Bt + (size_t)(bx * TN) * K;
    const int nk = K / KC;

    const int lrow = tid >> 3;
    const int lseg = tid & 7;

    float acc[4][8][4];
#pragma unroll
    for (int i = 0; i < 4; i++)
#pragma unroll
        for (int j = 0; j < 8; j++)
#pragma unroll
            for (int z = 0; z < 4; z++) acc[i][j][z] = 0.f;

    auto load_chunk = [&](int j) {
        uint32_t st = sb + (j & 3) * STGB;
#pragma unroll
        for (int i = 0; i < 8; i++) {
            int r = i * 32 + lrow;
            uint32_t off = (uint32_t)(r * 128 + lseg * 16);
            CP_ASYNC16(st + SWZ128(off), Ab + (size_t)r * K + j * KC + lseg * 8);
        }
        uint32_t stB = st + ASZ;
#pragma unroll
        for (int i = 0; i < 4; i++) {
            int r = i * 32 + lrow;
            uint32_t off = (uint32_t)(r * 128 + lseg * 16);
            CP_ASYNC16(stB + SWZ128(off), Bb + (size_t)r * K + j * KC + lseg * 8);
        }
        CP_COMMIT();
    };

    auto compute_chunk = [&](int it) {
        const uint32_t sA = sb + (it & 3) * STGB;
        const uint32_t sB = sA + ASZ;
#pragma unroll
        for (int kk = 0; kk < 4; kk++) {
            const int k0 = kk * 8;
            uint32_t af[4][4];
#pragma unroll
            for (int mf = 0; mf < 4; mf++) {
                int r0 = wm * 64 + mf * 16 + g;
                uint32_t ro = sA + r0 * 128;
                uint32_t kx = (uint32_t)((r0 & 7) << 4);
                uint32_t kl = ((uint32_t)((k0 + tg) * 4)) ^ kx;
                uint32_t kh = ((uint32_t)((k0 + tg + 4) * 4)) ^ kx;
                af[mf][0] = lds_u32(ro + kl);
                af[mf][1] = lds_u32(ro + 1024 + kl);
                af[mf][2] = lds_u32(ro + kh);
                af[mf][3] = lds_u32(ro + 1024 + kh);
            }
            uint32_t bf[8][2];
#pragma unroll
            for (int nf = 0; nf < 8; nf++) {
                int r = wn * 64 + nf * 8 + g;
                uint32_t ro = sB + r * 128;
                uint32_t kx = (uint32_t)((r & 7) << 4);
                bf[nf][0] = lds_u32(ro + (((uint32_t)((k0 + tg) * 4)) ^ kx));
                bf[nf][1] = lds_u32(ro + (((uint32_t)((k0 + tg + 4) * 4)) ^ kx));
            }
#pragma unroll
            for (int mf = 0; mf < 4; mf++)
#pragma unroll
                for (int nf = 0; nf < 8; nf++)
                    mma_f16(acc[mf][nf], af[mf], bf[nf]);
        }
    };

    load_chunk(0);
    load_chunk(1);

    for (int it = 0; it < nk; it += 2) {
        asm volatile("cp.async.wait_group 0;" ::: "memory");
        __syncthreads();
        if (it + 2 < nk) {
            load_chunk(it + 2);
            load_chunk(it + 3);
        }
        compute_chunk(it);
        compute_chunk(it + 1);
    }

    // ---- epilogue ----
#pragma unroll
    for (int mf = 0; mf < 4; mf++) {
#pragma unroll
        for (int half = 0; half < 2; half++) {
            int row = by * TM + wm * 64 + mf * 16 + g + half * 8;
            if (MODE == 2) {
                __half* Arow = (__half*)Cv + (size_t)row * (N / 2) + bx * (TN / 2) + wn * 32;
#pragma unroll
                for (int nf = 0; nf < 8; nf++) {
                    float gv = acc[mf][nf][half * 2 + 0];
                    float uv = acc[mf][nf][half * 2 + 1];
                    Arow[nf * 4 + tg] = __float2half_rn(gv / (1.f + __expf(-gv)) * uv);
                }
            } else if (MODE == 3) {
                __half* Crow = (__half*)Cv + (size_t)row * N + bx * TN + wn * 64;
#pragma unroll
                for (int nf = 0; nf < 8; nf++) {
                    int col = nf * 8 + tg * 2;
                    *(__half2*)(Crow + col) =
                        __floats2half2_rn(acc[mf][nf][half * 2 + 0],
                                          acc[mf][nf][half * 2 + 1]);
                }
            } else {
                float* Crow = (float*)Cv + (size_t)row * N + bx * TN + wn * 64;
                const float* Rrow = (MODE == 1)
                    ? (R + (size_t)row * N + bx * TN + wn * 64) : (const float*)0;
#pragma unroll
                for (int nf = 0; nf < 8; nf++) {
                    int col = nf * 8 + tg * 2;
                    float2 v = make_float2(acc[mf][nf][half * 2 + 0],
                                           acc[mf][nf][half * 2 + 1]);
                    if (MODE == 1) {
                        v.x += Rrow[col];
                        v.y += Rrow[col + 1];
                    }
                    *(float2*)(Crow + col) = v;
                }
            }
        }
    }
}

// ---------------- weight transpose + fp16 convert ----------------
template <int INTERLEAVE>
__global__ void transpose_round_kernel(const float* __restrict__ in,
                                       __half* __restrict__ out, int K, int N) {
    __shared__ float tt[64][65];
    int n0 = blockIdx.x * 64, k0 = blockIdx.y * 64;
    int tx = threadIdx.x, ty = threadIdx.y;
#pragma unroll
    for (int r = 0; r < 4; r++) {
        int k = k0 + ty + r * 16;
        float4 v = *(const float4*)(in + (size_t)k * N + n0 + 4 * tx);
        tt[4 * tx + 0][ty + r * 16] = v.x;
        tt[4 * tx + 1][ty + r * 16] = v.y;
        tt[4 * tx + 2][ty + r * 16] = v.z;
        tt[4 * tx + 3][ty + r * 16] = v.w;
    }
    __syncthreads();
#pragma unroll
    for (int r = 0; r < 4; r++) {
        int nl = ty + r * 16;
        int n = n0 + nl;
        size_t rowI;
        if (INTERLEAVE)
            rowI = (n < INTD) ? (size_t)(2 * n) : (size_t)(2 * (n - INTD) + 1);
        else
            rowI = (size_t)n;
        __half2 h01 = __floats2half2_rn(tt[nl][4 * tx + 0], tt[nl][4 * tx + 1]);
        __half2 h23 = __floats2half2_rn(tt[nl][4 * tx + 2], tt[nl][4 * tx + 3]);
        __half2* dst = (__half2*)(out + rowI * K + k0 + 4 * tx);
        dst[0] = h01;
        dst[1] = h23;
    }
}

// ---------------- RMSNorm (fp16 output) ----------------
__global__ void rmsnorm_kernel(const float* __restrict__ x, const float* __restrict__ w,
                               __half* __restrict__ out) {
    int row = blockIdx.x;
    const float* xr = x + (size_t)row * HIDD;
    __shared__ float red[256];
    float4 vals[2];
    float s = 0.f;
#pragma unroll
    for (int i = 0; i < 2; i++) {
        float4 v = *(const float4*)(xr + (threadIdx.x + i * 256) * 4);
        vals[i] = v;
        s += v.x * v.x + v.y * v.y + v.z * v.z + v.w * v.w;
    }
    red[threadIdx.x] = s;
    __syncthreads();
    for (int off = 128; off > 0; off >>= 1) {
        if (threadIdx.x < off) red[threadIdx.x] += red[threadIdx.x + off];
        __syncthreads();
    }
    float inv = rsqrtf(red[0] / (float)HIDD + 1e-6f);
#pragma unroll
    for (int i = 0; i < 2; i++) {
        int c = (threadIdx.x + i * 256) * 4;
        float4 v = vals[i];
        float4 wv = *(const float4*)(w + c);
        __half2 h01 = __floats2half2_rn(v.x * inv * wv.x, v.y * inv * wv.y);
        __half2 h23 = __floats2half2_rn(v.z * inv * wv.z, v.w * inv * wv.w);
        __half2* dst = (__half2*)(out + (size_t)row * HIDD + c);
        dst[0] = h01;
        dst[1] = h23;
    }
}

// ---------------- RoPE (in-place on fp16 qkv; fp32 math) ----------------
__global__ void rope_kernel(__half* __restrict__ qkv, const int* __restrict__ pos) {
    __shared__ float cs[64], sn[64];
    int tok = blockIdx.x;
    int p = pos[tok % SQ];
    if (threadIdx.x < 64) {
        double freq = exp(-(double)threadIdx.x * (9.210340371976184 / 64.0));
        float ang = (float)((double)p * freq);
        float s, c;
        sincosf(ang, &s, &c);
        cs[threadIdx.x] = c;
        sn[threadIdx.x] = s;
    }
    __syncthreads();
    __half2* base = (__half2*)(qkv + (size_t)tok * QKVD);
    for (int item = threadIdx.x; item < (NH + NKV) * 32; item += blockDim.x) {
        int head = item >> 5;
        int d2 = item & 31;
        float cx = cs[2 * d2], cy = cs[2 * d2 + 1];
        float sx = sn[2 * d2], sy = sn[2 * d2 + 1];
        __half2* p1 = base + head * 64 + d2;
        __half2* p2 = base + head * 64 + 32 + d2;
        float2 t1 = __half22float2(*p1);
        float2 t2 = __half22float2(*p2);
        *p1 = __floats2half2_rn(t1.x * cx - t2.x * sx, t1.y * cy - t2.y * sy);
        *p2 = __floats2half2_rn(t2.x * cx + t1.x * sx, t2.y * cy + t1.y * sy);
    }
}

// ---------------- fp16 tensor-core flash attention (causal, GQA) ----------------
// grid (SQ/128, NH, BATCH), 256 threads (8 warps x 16 q-rows).
// Pitches (32-bit words): Q/K = 68 (banks 4g+tg), V(pair-interleaved half2) = 136
// (banks 8tg+g), P(fp16) = 36 (banks 4g+tg). All fragment LDS conflict-free & batched.
#define QPW 68
#define VPW 136
#define PPW 36
#define ATTN_SMEM ((128 * QPW + 64 * QPW + 32 * VPW + 128 * PPW) * 4)

__global__ __launch_bounds__(256, 1) void attn_mma_kernel(const __half* __restrict__ qkv,
                                                          __half* __restrict__ attn_out) {
    extern __shared__ uint32_t smw[];
    uint32_t* Qs = smw;                       // 128 x QPW words
    uint32_t* Ks = Qs + 128 * QPW;            // 64 x QPW
    uint32_t* Vs = Ks + 64 * QPW;             // 32 x VPW  (key-pair half2)
    uint32_t* Ps = Vs + 32 * VPW;             // 128 x PPW (fp16)

    const int qt = (gridDim.x - 1) - blockIdx.x;
    const int h = blockIdx.y, b = blockIdx.z;
    const int kvh = h / (NH / NKV);
    const int tid = threadIdx.x, w = tid >> 5, lane = tid & 31;
    const int g = lane >> 2, tg = lane & 3;
    const int tokQ0 = b * SQ + qt * 128;

    const uint32_t sQ = smem_u32(Qs), sK = smem_u32(Ks), sV = smem_u32(Vs),
                   sP = smem_u32(Ps);

    // load Q tile (128 x 128 halves): uint4 = 8 halves = 4 words
#pragma unroll
    for (int t = 0; t < 8; t++) {
        int i = tid + t * 256;
        int r = i >> 4, s8 = (i & 15) * 8;
        uint4 v = *(const uint4*)(qkv + (size_t)(tokQ0 + r) * QKVD + h * HDIM + s8);
        *(uint4*)(Qs + r * QPW + s8 / 2) = v;
    }

    float o[16][4];
#pragma unroll
    for (int nf = 0; nf < 16; nf++)
#pragma unroll
        for (int z = 0; z < 4; z++) o[nf][z] = 0.f;
    float m0 = -1e30f, m1 = -1e30f, l0 = 0.f, l1 = 0.f;
    const float scale = 0.08838834764831845f;

    const int row0 = qt * 128 + w * 16 + g;
    const int ntile = 2 * qt + 2;

    for (int kt = 0; kt < ntile; kt++) {
        __syncthreads();
        {
            int tokK0 = b * SQ + kt * 64;
            // K tile: 64 rows x 128 halves
#pragma unroll
            for (int t = 0; t < 4; t++) {
                int i = tid + t * 256;
                int r = i >> 4, s8 = (i & 15) * 8;
                uint4 v = *(const uint4*)(qkv + (size_t)(tokK0 + r) * QKVD +
                                          (NH + kvh) * HDIM + s8);
                *(uint4*)(Ks + r * QPW + s8 / 2) = v;
            }
            // V tile: pair-interleave rows 2pr,2pr+1 into half2 words
#pragma unroll
            for (int t = 0; t < 2; t++) {
                int i = tid + t * 256;
                int pr = i >> 4, s8 = (i & 15) * 8;
                const __half* vb = qkv + (size_t)(tokK0 + 2 * pr) * QKVD +
                                   (NH + NKV + kvh) * HDIM + s8;
                uint4 a = *(const uint4*)(vb);
                uint4 bq = *(const uint4*)(vb + QKVD);
                uint32_t wds[8];
                asm("prmt.b32 %0, %1, %2, 0x5410;" : "=r"(wds[0]) : "r"(a.x), "r"(bq.x));
                asm("prmt.b32 %0, %1, %2, 0x7632;" : "=r"(wds[1]) : "r"(a.x), "r"(bq.x));
                asm("prmt.b32 %0, %1, %2, 0x5410;" : "=r"(wds[2]) : "r"(a.y), "r"(bq.y));
                asm("prmt.b32 %0, %1, %2, 0x7632;" : "=r"(wds[3]) : "r"(a.y), "r"(bq.y));
                asm("prmt.b32 %0, %1, %2, 0x5410;" : "=r"(wds[4]) : "r"(a.z), "r"(bq.z));
                asm("prmt.b32 %0, %1, %2, 0x7632;" : "=r"(wds[5]) : "r"(a.z), "r"(bq.z));
                asm("prmt.b32 %0, %1, %2, 0x5410;" : "=r"(wds[6]) : "r"(a.w), "r"(bq.w));
                asm("prmt.b32 %0, %1, %2, 0x7632;" : "=r"(wds[7]) : "r"(a.w), "r"(bq.w));
                uint32_t* dst = Vs + pr * VPW + s8;
                *(uint4*)(dst) = make_uint4(wds[0], wds[1], wds[2], wds[3]);
                *(uint4*)(dst + 4) = make_uint4(wds[4], wds[5], wds[6], wds[7]);
            }
        }
        __syncthreads();

        if (kt * 64 > qt * 128 + w * 16 + 15) continue;

        // ---- S = Q @ K^T (16 x 64, k=128 halves, 8 mma-k steps) ----
        float s[8][4];
#pragma unroll
        for (int nf = 0; nf < 8; nf++)
#pragma unroll
            for (int z = 0; z < 4; z++) s[nf][z] = 0.f;

        const uint32_t qrow = sQ + (uint32_t)((w * 16 + g) * QPW) * 4;
#pragma unroll
        for (int ks = 0; ks < 8; ks++) {
            uint32_t ko = (uint32_t)(ks * 8 + tg) * 4;
            uint32_t a[4];
            a[0] = lds_u32(qrow + ko);
            a[1] = lds_u32(qrow + (uint32_t)(8 * QPW) * 4 + ko);
            a[2] = lds_u32(qrow + ko + 16);
            a[3] = lds_u32(qrow + (uint32_t)(8 * QPW) * 4 + ko + 16);
            uint32_t bq[8][2];
#pragma unroll
            for (int nf = 0; nf < 8; nf++) {
                uint32_t krow = sK + (uint32_t)((nf * 8 + g) * QPW) * 4;
                bq[nf][0] = lds_u32(krow + ko);
                bq[nf][1] = lds_u32(krow + ko + 16);
            }
#pragma unroll
            for (int nf = 0; nf < 8; nf++)
                mma_f16(s[nf], a, bq[nf]);
        }

        // ---- online softmax ----
        const bool domask = (kt >= 2 * qt);
        float mx0 = -1e30f, mx1 = -1e30f;
#pragma unroll
        for (int nf = 0; nf < 8; nf++) {
#pragma unroll
            for (int z = 0; z < 4; z++) {
                float v = s[nf][z] * scale;
                if (domask) {
                    int col = kt * 64 + nf * 8 + 2 * tg + (z & 1);
                    int row = (z < 2) ? row0 : row0 + 8;
                    if (col > row) v = -1e30f;
                }
                s[nf][z] = v;
            }
            mx0 = fmaxf(mx0, fmaxf(s[nf][0], s[nf][1]));
            mx1 = fmaxf(mx1, fmaxf(s[nf][2], s[nf][3]));
        }
        mx0 = fmaxf(mx0, __shfl_xor_sync(0xffffffffu, mx0, 1));
        mx0 = fmaxf(mx0, __shfl_xor_sync(0xffffffffu, mx0, 2));
        mx1 = fmaxf(mx1, __shfl_xor_sync(0xffffffffu, mx1, 1));
        mx1 = fmaxf(mx1, __shfl_xor_sync(0xffffffffu, mx1, 2));
        float mn0 = fmaxf(m0, mx0), mn1 = fmaxf(m1, mx1);
        float c0 = __expf(m0 - mn0), c1 = __expf(m1 - mn1);
        float sum0 = 0.f, sum1 = 0.f;
        uint32_t prow0 = sP + (uint32_t)((w * 16 + g) * PPW) * 4;
        uint32_t prow1 = prow0 + (uint32_t)(8 * PPW) * 4;
#pragma unroll
        for (int nf = 0; nf < 8; nf++) {
            float p0 = __expf(s[nf][0] - mn0);
            float p1 = __expf(s[nf][1] - mn0);
            float p2 = __expf(s[nf][2] - mn1);
            float p3 = __expf(s[nf][3] - mn1);
            sum0 += p0 + p1;
            sum1 += p2 + p3;
            uint32_t w01 = h2_as_u32(__floats2half2_rn(p0, p1));
            uint32_t w23 = h2_as_u32(__floats2half2_rn(p2, p3));
            uint32_t wo = (uint32_t)(nf * 4 + tg) * 4;
            asm volatile("st.shared.b32 [%0], %1;" :: "r"(prow0 + wo), "r"(w01) : "memory");
            asm volatile("st.shared.b32 [%0], %1;" :: "r"(prow1 + wo), "r"(w23) : "memory");
        }
        sum0 += __shfl_xor_sync(0xffffffffu, sum0, 1);
        sum0 += __shfl_xor_sync(0xffffffffu, sum0, 2);
        sum1 += __shfl_xor_sync(0xffffffffu, sum1, 1);
        sum1 += __shfl_xor_sync(0xffffffffu, sum1, 2);
        l0 = l0 * c0 + sum0;
        l1 = l1 * c1 + sum1;
        m0 = mn0; m1 = mn1;
#pragma unroll
        for (int nf = 0; nf < 16; nf++) {
            o[nf][0] *= c0; o[nf][1] *= c0;
            o[nf][2] *= c1; o[nf][3] *= c1;
        }
        __syncwarp();

        // ---- O += P @ V (16 x 128, k=64 keys, 4 mma-k steps) ----
        const uint32_t prow = sP + (uint32_t)((w * 16 + g) * PPW) * 4;
#pragma unroll
        for (int ks = 0; ks < 4; ks++) {
            uint32_t ko = (uint32_t)(ks * 8 + tg) * 4;
            uint32_t a[4];
            a[0] = lds_u32(prow + ko);
            a[1] = lds_u32(prow + (uint32_t)(8 * PPW) * 4 + ko);
            a[2] = lds_u32(prow + ko + 16);
            a[3] = lds_u32(prow + (uint32_t)(8 * PPW) * 4 + ko + 16);
            uint32_t v0 = sV + (uint32_t)((ks * 8 + tg) * VPW + g) * 4;
            uint32_t v1 = v0 + (uint32_t)(4 * VPW) * 4;
            uint32_t bv[16][2];
#pragma unroll
            for (int nf = 0; nf < 16; nf++) {
                bv[nf][0] = lds_u32(v0 + nf * 32);
                bv[nf][1] = lds_u32(v1 + nf * 32);
            }
#pragma unroll
            for (int nf = 0; nf < 16; nf++)
                mma_f16(o[nf], a, bv[nf]);
        }
    }

    float inv0 = 1.f / l0, inv1 = 1.f / l1;
    __half* orow0 = attn_out + (size_t)(tokQ0 + w * 16 + g) * HIDD + h * HDIM;
    __half* orow1 = orow0 + (size_t)8 * HIDD;
#pragma unroll
    for (int nf = 0; nf < 16; nf++) {
        int col = nf * 8 + 2 * tg;
        *(__half2*)(orow0 + col) = __floats2half2_rn(o[nf][0] * inv0, o[nf][1] * inv0);
        *(__half2*)(orow1 + col) = __floats2half2_rn(o[nf][2] * inv1, o[nf][3] * inv1);
    }
}

extern "C" void kernel_launch(void* const* d_in, const int* in_sizes, int n_in,
                              void* d_out, int out_size) {
    const float* x    = (const float*)d_in[0];
    const float* ln1  = (const float*)d_in[1];
    const float* wqkv = (const float*)d_in[2];
    const float* wo   = (const float*)d_in[3];
    const float* ln2  = (const float*)d_in[4];
    const float* wgu  = (const float*)d_in[5];
    const float* wdn  = (const float*)d_in[6];
    const int*   pos  = (const int*)d_in[7];
    float* out = (float*)d_out;

    void *xn, *qkvh, *attn, *h1, *h2, *act;
    void *wqkvT, *woT, *wguT, *wdnT;
    cudaGetSymbolAddress(&xn, g_xn);
    cudaGetSymbolAddress(&qkvh, g_qkvh);
    cudaGetSymbolAddress(&attn, g_attn);
    cudaGetSymbolAddress(&h1, g_h1);
    cudaGetSymbolAddress(&h2, g_h2);
    cudaGetSymbolAddress(&act, g_act);
    cudaGetSymbolAddress(&wqkvT, g_wqkvT);
    cudaGetSymbolAddress(&woT, g_woT);
    cudaGetSymbolAddress(&wguT, g_wguT);
    cudaGetSymbolAddress(&wdnT, g_wdnT);

    cudaFuncSetAttribute(attn_mma_kernel, cudaFuncAttributeMaxDynamicSharedMemorySize, ATTN_SMEM);
    cudaFuncSetAttribute(tc_gemm<0>, cudaFuncAttributeMaxDynamicSharedMemorySize, GEMM_SMEM_TC);
    cudaFuncSetAttribute(tc_gemm<1>, cudaFuncAttributeMaxDynamicSharedMemorySize, GEMM_SMEM_TC);
    cudaFuncSetAttribute(tc_gemm<2>, cudaFuncAttributeMaxDynamicSharedMemorySize, GEMM_SMEM_TC);
    cudaFuncSetAttribute(tc_gemm<3>, cudaFuncAttributeMaxDynamicSharedMemorySize, GEMM_SMEM_TC);

    // 0. weight transpose + fp16 convert (gate_up interleaved)
    {
        dim3 bb(16, 16);
        transpose_round_kernel<0><<<dim3(QKVD / 64, HIDD / 64), bb>>>(wqkv, (__half*)wqkvT, HIDD, QKVD);
        transpose_round_kernel<0><<<dim3(HIDD / 64, HIDD / 64), bb>>>(wo, (__half*)woT, HIDD, HIDD);
        transpose_round_kernel<1><<<dim3(2 * INTD / 64, HIDD / 64), bb>>>(wgu, (__half*)wguT, HIDD, 2 * INTD);
        transpose_round_kernel<0><<<dim3(HIDD / 64, INTD / 64), bb>>>(wdn, (__half*)wdnT, INTD, HIDD);
    }
    // 1. h = rmsnorm(x, ln1)  (fp16)
    rmsnorm_kernel<<<NTOK, 256>>>(x, ln1, (__half*)xn);
    // 2. qkv = h @ wqkv  (fp16 out)
    tc_gemm<3><<<dim3(NTOK / TM, QKVD / TN), 256, GEMM_SMEM_TC>>>(
        (const __half*)xn, (const __half*)wqkvT, nullptr, qkvh, QKVD, HIDD);
    // 3. RoPE (in-place fp16)
    rope_kernel<<<NTOK, 256>>>((__half*)qkvh, pos);
    // 4. attention (fp16 mma, fp16 out)
    {
        dim3 g(SQ / 128, NH, BATCH);
        attn_mma_kernel<<<g, 256, ATTN_SMEM>>>((const __half*)qkvh, (__half*)attn);
    }
    // 5. h1 = x + attn @ wo  (fp32 out)
    tc_gemm<1><<<dim3(NTOK / TM, HIDD / TN), 256, GEMM_SMEM_TC>>>(
        (const __half*)attn, (const __half*)woT, x, h1, HIDD, HIDD);
    // 6. h2 = rmsnorm(h1, ln2)  (fp16)
    rmsnorm_kernel<<<NTOK, 256>>>((const float*)h1, ln2, (__half*)h2);
    // 7+8. act = silu(h2 @ w_gate) * (h2 @ w_up)  (fp16, fused epilogue)
    tc_gemm<2><<<dim3(NTOK / TM, 2 * INTD / TN), 256, GEMM_SMEM_TC>>>(
        (const __half*)h2, (const __half*)wguT, nullptr, act, 2 * INTD, HIDD);
    // 9. out = h1 + act @ w_down  (fp32 out)
    tc_gemm<1><<<dim3(NTOK / TM, HIDD / TN), 256, GEMM_SMEM_TC>>>(
        (const __half*)act, (const __half*)wdnT, (const float*)h1, out, HIDD, INTD);
}

// round 15
// speedup vs baseline: 3.5488x; 1.0209x over previous
#include <cuda_runtime.h>
#include <cuda_fp16.h>
#include <math.h>
#include <stdint.h>

#define NTOK 4096
#define SQ   1024
#define BATCH 4
#define HIDD 2048
#define NH   16
#define NKV  4
#define HDIM 128
#define QKVD 3072   // (16+2*4)*128
#define INTD 8192

// ---------------- scratch (static device memory; no allocations) ----------------
__device__ __half g_xn  [(size_t)NTOK * HIDD];
__device__ __half g_qkvh[(size_t)NTOK * QKVD];
__device__ __half g_attn[(size_t)NTOK * HIDD];
__device__ float  g_h1  [(size_t)NTOK * HIDD];
__device__ __half g_h2  [(size_t)NTOK * HIDD];
__device__ __half g_act [(size_t)NTOK * INTD];
// transposed fp16 weights [N, K] K-major
__device__ __half g_wqkvT [(size_t)QKVD * HIDD];
__device__ __half g_woT   [(size_t)HIDD * HIDD];
__device__ __half g_wguT  [(size_t)2 * INTD * HIDD];  // interleaved: row 2j=gate_j, 2j+1=up_j
__device__ __half g_wdnT  [(size_t)HIDD * INTD];

// ---------------- helpers ----------------
__device__ __forceinline__ uint32_t h2_as_u32(__half2 h) {
    uint32_t u;
    asm("mov.b32 %0, %1;" : "=r"(u) : "r"(*(unsigned int*)&h));
    return u;
}

__device__ __forceinline__ uint32_t smem_u32(const void* p) {
    uint32_t a;
    asm("{ .reg .u64 t; cvta.to.shared.u64 t, %1; cvt.u32.u64 %0, t; }"
        : "=r"(a) : "l"(p));
    return a;
}

__device__ __forceinline__ uint32_t lds_u32(uint32_t a) {
    uint32_t v;
    asm volatile("ld.shared.b32 %0, [%1];" : "=r"(v) : "r"(a));
    return v;
}

#define SWZ128(o) ((o) ^ (((o) >> 3) & 0x70))

#define CP_ASYNC16(dst, src) \
    asm volatile("cp.async.cg.shared.global [%0], [%1], 16;" :: "r"(dst), "l"(src) : "memory")
#define CP_COMMIT() asm volatile("cp.async.commit_group;" ::: "memory")

__device__ __forceinline__ void mma_f16(float* c, const uint32_t* a, const uint32_t* b) {
    asm volatile(
        "mma.sync.aligned.m16n8k16.row.col.f32.f16.f16.f32 "
        "{%0,%1,%2,%3}, {%4,%5,%6,%7}, {%8,%9}, {%0,%1,%2,%3};\n"
        : "+f"(c[0]), "+f"(c[1]), "+f"(c[2]), "+f"(c[3])
        : "r"(a[0]), "r"(a[1]), "r"(a[2]), "r"(a[3]), "r"(b[0]), "r"(b[1]));
}

// ---------------- HMMA fp16 GEMM: tile 256(M)x128(N), KC=64 halves, 4-stage, 2/sync ----
// MODE: 0 = fp32 out, 1 = +fp32 residual, 2 = silu-fused fp16 out, 3 = plain fp16 out
#define TM 256
#define TN 128
#define KC 64
#define NSTG 4
#define ASZ (TM * KC * 2)
#define BSZ (TN * KC * 2)
#define STGB (ASZ + BSZ)
#define GEMM_SMEM_TC (NSTG * STGB)   // 196608 B

template <int MODE>
__global__ __launch_bounds__(256, 1) void tc_gemm(const __half* __restrict__ A,
                                                  const __half* __restrict__ Bt,
                                                  const float* __restrict__ R,
                                                  void* __restrict__ Cv,
                                                  int N, int K) {
    extern __shared__ char smc[];
    const uint32_t sb = smem_u32(smc);
    const int tid = threadIdx.x;
    const int lane = tid & 31, w = tid >> 5;
    const int wm = w >> 1, wn = w & 1;
    const int g = lane >> 2, tg = lane & 3;
    const int by = blockIdx.x, bx = blockIdx.y;

    const __half* Ab = A + (size_t)(by * TM) * K;
    const __half* Bb = Bt + (size_t)(bx * TN) * K;
    const int nk = K / KC;

    const int lrow = tid >> 3;
    const int lseg = tid & 7;

    float acc[4][8][4];
#pragma unroll
    for (int i = 0; i < 4; i++)
#pragma unroll
        for (int j = 0; j < 8; j++)
#pragma unroll
            for (int z = 0; z < 4; z++) acc[i][j][z] = 0.f;

    auto load_chunk = [&](int j) {
        uint32_t st = sb + (j & 3) * STGB;
#pragma unroll
        for (int i = 0; i < 8; i++) {
            int r = i * 32 + lrow;
            uint32_t off = (uint32_t)(r * 128 + lseg * 16);
            CP_ASYNC16(st + SWZ128(off), Ab + (size_t)r * K + j * KC + lseg * 8);
        }
        uint32_t stB = st + ASZ;
#pragma unroll
        for (int i = 0; i < 4; i++) {
            int r = i * 32 + lrow;
            uint32_t off = (uint32_t)(r * 128 + lseg * 16);
            CP_ASYNC16(stB + SWZ128(off), Bb + (size_t)r * K + j * KC + lseg * 8);
        }
        CP_COMMIT();
    };

    auto compute_chunk = [&](int it) {
        const uint32_t sA = sb + (it & 3) * STGB;
        const uint32_t sB = sA + ASZ;
#pragma unroll
        for (int kk = 0; kk < 4; kk++) {
            const int k0 = kk * 8;
            uint32_t af[4][4];
#pragma unroll
            for (int mf = 0; mf < 4; mf++) {
                int r0 = wm * 64 + mf * 16 + g;
                uint32_t ro = sA + r0 * 128;
                uint32_t kx = (uint32_t)((r0 & 7) << 4);
                uint32_t kl = ((uint32_t)((k0 + tg) * 4)) ^ kx;
                uint32_t kh = ((uint32_t)((k0 + tg + 4) * 4)) ^ kx;
                af[mf][0] = lds_u32(ro + kl);
                af[mf][1] = lds_u32(ro + 1024 + kl);
                af[mf][2] = lds_u32(ro + kh);
                af[mf][3] = lds_u32(ro + 1024 + kh);
            }
            uint32_t bf[8][2];
#pragma unroll
            for (int nf = 0; nf < 8; nf++) {
                int r = wn * 64 + nf * 8 + g;
                uint32_t ro = sB + r * 128;
                uint32_t kx = (uint32_t)((r & 7) << 4);
                bf[nf][0] = lds_u32(ro + (((uint32_t)((k0 + tg) * 4)) ^ kx));
                bf[nf][1] = lds_u32(ro + (((uint32_t)((k0 + tg + 4) * 4)) ^ kx));
            }
#pragma unroll
            for (int mf = 0; mf < 4; mf++)
#pragma unroll
                for (int nf = 0; nf < 8; nf++)
                    mma_f16(acc[mf][nf], af[mf], bf[nf]);
        }
    };

    load_chunk(0);
    load_chunk(1);

    for (int it = 0; it < nk; it += 2) {
        asm volatile("cp.async.wait_group 0;" ::: "memory");
        __syncthreads();
        if (it + 2 < nk) {
            load_chunk(it + 2);
            load_chunk(it + 3);
        }
        compute_chunk(it);
        compute_chunk(it + 1);
    }

    // ---- epilogue ----
#pragma unroll
    for (int mf = 0; mf < 4; mf++) {
#pragma unroll
        for (int half = 0; half < 2; half++) {
            int row = by * TM + wm * 64 + mf * 16 + g + half * 8;
            if (MODE == 2) {
                __half* Arow = (__half*)Cv + (size_t)row * (N / 2) + bx * (TN / 2) + wn * 32;
#pragma unroll
                for (int nf = 0; nf < 8; nf++) {
                    float gv = acc[mf][nf][half * 2 + 0];
                    float uv = acc[mf][nf][half * 2 + 1];
                    Arow[nf * 4 + tg] = __float2half_rn(gv / (1.f + __expf(-gv)) * uv);
                }
            } else if (MODE == 3) {
                __half* Crow = (__half*)Cv + (size_t)row * N + bx * TN + wn * 64;
#pragma unroll
                for (int nf = 0; nf < 8; nf++) {
                    int col = nf * 8 + tg * 2;
                    *(__half2*)(Crow + col) =
                        __floats2half2_rn(acc[mf][nf][half * 2 + 0],
                                          acc[mf][nf][half * 2 + 1]);
                }
            } else {
                float* Crow = (float*)Cv + (size_t)row * N + bx * TN + wn * 64;
                const float* Rrow = (MODE == 1)
                    ? (R + (size_t)row * N + bx * TN + wn * 64) : (const float*)0;
#pragma unroll
                for (int nf = 0; nf < 8; nf++) {
                    int col = nf * 8 + tg * 2;
                    float2 v = make_float2(acc[mf][nf][half * 2 + 0],
                                           acc[mf][nf][half * 2 + 1]);
                    if (MODE == 1) {
                        v.x += Rrow[col];
                        v.y += Rrow[col + 1];
                    }
                    *(float2*)(Crow + col) = v;
                }
            }
        }
    }
}

// ---------------- weight transpose + fp16 convert ----------------
template <int INTERLEAVE>
__global__ void transpose_round_kernel(const float* __restrict__ in,
                                       __half* __restrict__ out, int K, int N) {
    __shared__ float tt[64][65];
    int n0 = blockIdx.x * 64, k0 = blockIdx.y * 64;
    int tx = threadIdx.x, ty = threadIdx.y;
#pragma unroll
    for (int r = 0; r < 4; r++) {
        int k = k0 + ty + r * 16;
        float4 v = *(const float4*)(in + (size_t)k * N + n0 + 4 * tx);
        tt[4 * tx + 0][ty + r * 16] = v.x;
        tt[4 * tx + 1][ty + r * 16] = v.y;
        tt[4 * tx + 2][ty + r * 16] = v.z;
        tt[4 * tx + 3][ty + r * 16] = v.w;
    }
    __syncthreads();
#pragma unroll
    for (int r = 0; r < 4; r++) {
        int nl = ty + r * 16;
        int n = n0 + nl;
        size_t rowI;
        if (INTERLEAVE)
            rowI = (n < INTD) ? (size_t)(2 * n) : (size_t)(2 * (n - INTD) + 1);
        else
            rowI = (size_t)n;
        __half2 h01 = __floats2half2_rn(tt[nl][4 * tx + 0], tt[nl][4 * tx + 1]);
        __half2 h23 = __floats2half2_rn(tt[nl][4 * tx + 2], tt[nl][4 * tx + 3]);
        __half2* dst = (__half2*)(out + rowI * K + k0 + 4 * tx);
        dst[0] = h01;
        dst[1] = h23;
    }
}

// ---------------- RMSNorm (fp16 output) ----------------
__global__ void rmsnorm_kernel(const float* __restrict__ x, const float* __restrict__ w,
                               __half* __restrict__ out) {
    int row = blockIdx.x;
    const float* xr = x + (size_t)row * HIDD;
    __shared__ float red[256];
    float4 vals[2];
    float s = 0.f;
#pragma unroll
    for (int i = 0; i < 2; i++) {
        float4 v = *(const float4*)(xr + (threadIdx.x + i * 256) * 4);
        vals[i] = v;
        s += v.x * v.x + v.y * v.y + v.z * v.z + v.w * v.w;
    }
    red[threadIdx.x] = s;
    __syncthreads();
    for (int off = 128; off > 0; off >>= 1) {
        if (threadIdx.x < off) red[threadIdx.x] += red[threadIdx.x + off];
        __syncthreads();
    }
    float inv = rsqrtf(red[0] / (float)HIDD + 1e-6f);
#pragma unroll
    for (int i = 0; i < 2; i++) {
        int c = (threadIdx.x + i * 256) * 4;
        float4 v = vals[i];
        float4 wv = *(const float4*)(w + c);
        __half2 h01 = __floats2half2_rn(v.x * inv * wv.x, v.y * inv * wv.y);
        __half2 h23 = __floats2half2_rn(v.z * inv * wv.z, v.w * inv * wv.w);
        __half2* dst = (__half2*)(out + (size_t)row * HIDD + c);
        dst[0] = h01;
        dst[1] = h23;
    }
}

// ---------------- RoPE (in-place on fp16 qkv; fp32 math) ----------------
__global__ void rope_kernel(__half* __restrict__ qkv, const int* __restrict__ pos) {
    __shared__ float cs[64], sn[64];
    int tok = blockIdx.x;
    int p = pos[tok % SQ];
    if (threadIdx.x < 64) {
        double freq = exp(-(double)threadIdx.x * (9.210340371976184 / 64.0));
        float ang = (float)((double)p * freq);
        float s, c;
        sincosf(ang, &s, &c);
        cs[threadIdx.x] = c;
        sn[threadIdx.x] = s;
    }
    __syncthreads();
    __half2* base = (__half2*)(qkv + (size_t)tok * QKVD);
    for (int item = threadIdx.x; item < (NH + NKV) * 32; item += blockDim.x) {
        int head = item >> 5;
        int d2 = item & 31;
        float cx = cs[2 * d2], cy = cs[2 * d2 + 1];
        float sx = sn[2 * d2], sy = sn[2 * d2 + 1];
        __half2* p1 = base + head * 64 + d2;
        __half2* p2 = base + head * 64 + 32 + d2;
        float2 t1 = __half22float2(*p1);
        float2 t2 = __half22float2(*p2);
        *p1 = __floats2half2_rn(t1.x * cx - t2.x * sx, t1.y * cy - t2.y * sy);
        *p2 = __floats2half2_rn(t2.x * cx + t1.x * sx, t2.y * cy + t1.y * sy);
    }
}

// ---------------- fp16 tensor-core flash attention (causal, GQA) ----------------
#define QPW 68
#define VPW 136
#define PPW 36
#define ATTN_SMEM ((128 * QPW + 64 * QPW + 32 * VPW + 128 * PPW) * 4)

__global__ __launch_bounds__(256, 1) void attn_mma_kernel(const __half* __restrict__ qkv,
                                                          __half* __restrict__ attn_out) {
    extern __shared__ uint32_t smw[];
    uint32_t* Qs = smw;                       // 128 x QPW words
    uint32_t* Ks = Qs + 128 * QPW;            // 64 x QPW
    uint32_t* Vs = Ks + 64 * QPW;             // 32 x VPW  (key-pair half2)
    uint32_t* Ps = Vs + 32 * VPW;             // 128 x PPW (fp16)

    const int qt = (gridDim.x - 1) - blockIdx.x;
    const int h = blockIdx.y, b = blockIdx.z;
    const int kvh = h / (NH / NKV);
    const int tid = threadIdx.x, w = tid >> 5, lane = tid & 31;
    const int g = lane >> 2, tg = lane & 3;
    const int tokQ0 = b * SQ + qt * 128;

    const uint32_t sQ = smem_u32(Qs), sK = smem_u32(Ks), sV = smem_u32(Vs),
                   sP = smem_u32(Ps);

#pragma unroll
    for (int t = 0; t < 8; t++) {
        int i = tid + t * 256;
        int r = i >> 4, s8 = (i & 15) * 8;
        uint4 v = *(const uint4*)(qkv + (size_t)(tokQ0 + r) * QKVD + h * HDIM + s8);
        *(uint4*)(Qs + r * QPW + s8 / 2) = v;
    }

    float o[16][4];
#pragma unroll
    for (int nf = 0; nf < 16; nf++)
#pragma unroll
        for (int z = 0; z < 4; z++) o[nf][z] = 0.f;
    float m0 = -1e30f, m1 = -1e30f, l0 = 0.f, l1 = 0.f;
    const float scale = 0.08838834764831845f;

    const int row0 = qt * 128 + w * 16 + g;
    const int ntile = 2 * qt + 2;

    for (int kt = 0; kt < ntile; kt++) {
        __syncthreads();
        {
            int tokK0 = b * SQ + kt * 64;
#pragma unroll
            for (int t = 0; t < 4; t++) {
                int i = tid + t * 256;
                int r = i >> 4, s8 = (i & 15) * 8;
                uint4 v = *(const uint4*)(qkv + (size_t)(tokK0 + r) * QKVD +
                                          (NH + kvh) * HDIM + s8);
                *(uint4*)(Ks + r * QPW + s8 / 2) = v;
            }
#pragma unroll
            for (int t = 0; t < 2; t++) {
                int i = tid + t * 256;
                int pr = i >> 4, s8 = (i & 15) * 8;
                const __half* vb = qkv + (size_t)(tokK0 + 2 * pr) * QKVD +
                                   (NH + NKV + kvh) * HDIM + s8;
                uint4 a = *(const uint4*)(vb);
                uint4 bq = *(const uint4*)(vb + QKVD);
                uint32_t wds[8];
                asm("prmt.b32 %0, %1, %2, 0x5410;" : "=r"(wds[0]) : "r"(a.x), "r"(bq.x));
                asm("prmt.b32 %0, %1, %2, 0x7632;" : "=r"(wds[1]) : "r"(a.x), "r"(bq.x));
                asm("prmt.b32 %0, %1, %2, 0x5410;" : "=r"(wds[2]) : "r"(a.y), "r"(bq.y));
                asm("prmt.b32 %0, %1, %2, 0x7632;" : "=r"(wds[3]) : "r"(a.y), "r"(bq.y));
                asm("prmt.b32 %0, %1, %2, 0x5410;" : "=r"(wds[4]) : "r"(a.z), "r"(bq.z));
                asm("prmt.b32 %0, %1, %2, 0x7632;" : "=r"(wds[5]) : "r"(a.z), "r"(bq.z));
                asm("prmt.b32 %0, %1, %2, 0x5410;" : "=r"(wds[6]) : "r"(a.w), "r"(bq.w));
                asm("prmt.b32 %0, %1, %2, 0x7632;" : "=r"(wds[7]) : "r"(a.w), "r"(bq.w));
                uint32_t* dst = Vs + pr * VPW + s8;
                *(uint4*)(dst) = make_uint4(wds[0], wds[1], wds[2], wds[3]);
                *(uint4*)(dst + 4) = make_uint4(wds[4], wds[5], wds[6], wds[7]);
            }
        }
        __syncthreads();

        if (kt * 64 > qt * 128 + w * 16 + 15) continue;

        float s[8][4];
#pragma unroll
        for (int nf = 0; nf < 8; nf++)
#pragma unroll
            for (int z = 0; z < 4; z++) s[nf][z] = 0.f;

        const uint32_t qrow = sQ + (uint32_t)((w * 16 + g) * QPW) * 4;
#pragma unroll
        for (int ks = 0; ks < 8; ks++) {
            uint32_t ko = (uint32_t)(ks * 8 + tg) * 4;
            uint32_t a[4];
            a[0] = lds_u32(qrow + ko);
            a[1] = lds_u32(qrow + (uint32_t)(8 * QPW) * 4 + ko);
            a[2] = lds_u32(qrow + ko + 16);
            a[3] = lds_u32(qrow + (uint32_t)(8 * QPW) * 4 + ko + 16);
            uint32_t bq[8][2];
#pragma unroll
            for (int nf = 0; nf < 8; nf++) {
                uint32_t krow = sK + (uint32_t)((nf * 8 + g) * QPW) * 4;
                bq[nf][0] = lds_u32(krow + ko);
                bq[nf][1] = lds_u32(krow + ko + 16);
            }
#pragma unroll
            for (int nf = 0; nf < 8; nf++)
                mma_f16(s[nf], a, bq[nf]);
        }

        const bool domask = (kt >= 2 * qt);
        float mx0 = -1e30f, mx1 = -1e30f;
#pragma unroll
        for (int nf = 0; nf < 8; nf++) {
#pragma unroll
            for (int z = 0; z < 4; z++) {
                float v = s[nf][z] * scale;
                if (domask) {
                    int col = kt * 64 + nf * 8 + 2 * tg + (z & 1);
                    int row = (z < 2) ? row0 : row0 + 8;
                    if (col > row) v = -1e30f;
                }
                s[nf][z] = v;
            }
            mx0 = fmaxf(mx0, fmaxf(s[nf][0], s[nf][1]));
            mx1 = fmaxf(mx1, fmaxf(s[nf][2], s[nf][3]));
        }
        mx0 = fmaxf(mx0, __shfl_xor_sync(0xffffffffu, mx0, 1));
        mx0 = fmaxf(mx0, __shfl_xor_sync(0xffffffffu, mx0, 2));
        mx1 = fmaxf(mx1, __shfl_xor_sync(0xffffffffu, mx1, 1));
        mx1 = fmaxf(mx1, __shfl_xor_sync(0xffffffffu, mx1, 2));
        float mn0 = fmaxf(m0, mx0), mn1 = fmaxf(m1, mx1);
        float c0 = __expf(m0 - mn0), c1 = __expf(m1 - mn1);
        float sum0 = 0.f, sum1 = 0.f;
        uint32_t prow0 = sP + (uint32_t)((w * 16 + g) * PPW) * 4;
        uint32_t prow1 = prow0 + (uint32_t)(8 * PPW) * 4;
#pragma unroll
        for (int nf = 0; nf < 8; nf++) {
            float p0 = __expf(s[nf][0] - mn0);
            float p1 = __expf(s[nf][1] - mn0);
            float p2 = __expf(s[nf][2] - mn1);
            float p3 = __expf(s[nf][3] - mn1);
            sum0 += p0 + p1;
            sum1 += p2 + p3;
            uint32_t w01 = h2_as_u32(__floats2half2_rn(p0, p1));
            uint32_t w23 = h2_as_u32(__floats2half2_rn(p2, p3));
            uint32_t wo = (uint32_t)(nf * 4 + tg) * 4;
            asm volatile("st.shared.b32 [%0], %1;" :: "r"(prow0 + wo), "r"(w01) : "memory");
            asm volatile("st.shared.b32 [%0], %1;" :: "r"(prow1 + wo), "r"(w23) : "memory");
        }
        sum0 += __shfl_xor_sync(0xffffffffu, sum0, 1);
        sum0 += __shfl_xor_sync(0xffffffffu, sum0, 2);
        sum1 += __shfl_xor_sync(0xffffffffu, sum1, 1);
        sum1 += __shfl_xor_sync(0xffffffffu, sum1, 2);
        l0 = l0 * c0 + sum0;
        l1 = l1 * c1 + sum1;
        m0 = mn0; m1 = mn1;
#pragma unroll
        for (int nf = 0; nf < 16; nf++) {
            o[nf][0] *= c0; o[nf][1] *= c0;
            o[nf][2] *= c1; o[nf][3] *= c1;
        }
        __syncwarp();

        const uint32_t prow = sP + (uint32_t)((w * 16 + g) * PPW) * 4;
#pragma unroll
        for (int ks = 0; ks < 4; ks++) {
            uint32_t ko = (uint32_t)(ks * 8 + tg) * 4;
            uint32_t a[4];
            a[0] = lds_u32(prow + ko);
            a[1] = lds_u32(prow + (uint32_t)(8 * PPW) * 4 + ko);
            a[2] = lds_u32(prow + ko + 16);
            a[3] = lds_u32(prow + (uint32_t)(8 * PPW) * 4 + ko + 16);
            uint32_t v0 = sV + (uint32_t)((ks * 8 + tg) * VPW + g) * 4;
            uint32_t v1 = v0 + (uint32_t)(4 * VPW) * 4;
            uint32_t bv[16][2];
#pragma unroll
            for (int nf = 0; nf < 16; nf++) {
                bv[nf][0] = lds_u32(v0 + nf * 32);
                bv[nf][1] = lds_u32(v1 + nf * 32);
            }
#pragma unroll
            for (int nf = 0; nf < 16; nf++)
                mma_f16(o[nf], a, bv[nf]);
        }
    }

    float inv0 = 1.f / l0, inv1 = 1.f / l1;
    __half* orow0 = attn_out + (size_t)(tokQ0 + w * 16 + g) * HIDD + h * HDIM;
    __half* orow1 = orow0 + (size_t)8 * HIDD;
#pragma unroll
    for (int nf = 0; nf < 16; nf++) {
        int col = nf * 8 + 2 * tg;
        *(__half2*)(orow0 + col) = __floats2half2_rn(o[nf][0] * inv0, o[nf][1] * inv0);
        *(__half2*)(orow1 + col) = __floats2half2_rn(o[nf][2] * inv1, o[nf][3] * inv1);
    }
}

extern "C" void kernel_launch(void* const* d_in, const int* in_sizes, int n_in,
                              void* d_out, int out_size) {
    const float* x    = (const float*)d_in[0];
    const float* ln1  = (const float*)d_in[1];
    const float* wqkv = (const float*)d_in[2];
    const float* wo   = (const float*)d_in[3];
    const float* ln2  = (const float*)d_in[4];
    const float* wgu  = (const float*)d_in[5];
    const float* wdn  = (const float*)d_in[6];
    const int*   pos  = (const int*)d_in[7];
    float* out = (float*)d_out;

    void *xn, *qkvh, *attn, *h1, *h2, *act;
    void *wqkvT, *woT, *wguT, *wdnT;
    cudaGetSymbolAddress(&xn, g_xn);
    cudaGetSymbolAddress(&qkvh, g_qkvh);
    cudaGetSymbolAddress(&attn, g_attn);
    cudaGetSymbolAddress(&h1, g_h1);
    cudaGetSymbolAddress(&h2, g_h2);
    cudaGetSymbolAddress(&act, g_act);
    cudaGetSymbolAddress(&wqkvT, g_wqkvT);
    cudaGetSymbolAddress(&woT, g_woT);
    cudaGetSymbolAddress(&wguT, g_wguT);
    cudaGetSymbolAddress(&wdnT, g_wdnT);

    cudaFuncSetAttribute(attn_mma_kernel, cudaFuncAttributeMaxDynamicSharedMemorySize, ATTN_SMEM);
    cudaFuncSetAttribute(tc_gemm<0>, cudaFuncAttributeMaxDynamicSharedMemorySize, GEMM_SMEM_TC);
    cudaFuncSetAttribute(tc_gemm<1>, cudaFuncAttributeMaxDynamicSharedMemorySize, GEMM_SMEM_TC);
    cudaFuncSetAttribute(tc_gemm<2>, cudaFuncAttributeMaxDynamicSharedMemorySize, GEMM_SMEM_TC);
    cudaFuncSetAttribute(tc_gemm<3>, cudaFuncAttributeMaxDynamicSharedMemorySize, GEMM_SMEM_TC);

    // ---- side stream for weight prep (fork/join via events; capture-legal) ----
    cudaStream_t side;
    cudaStreamCreateWithFlags(&side, cudaStreamNonBlocking);
    cudaEvent_t evF, evQ, evW;
    cudaEventCreateWithFlags(&evF, cudaEventDisableTiming);
    cudaEventCreateWithFlags(&evQ, cudaEventDisableTiming);
    cudaEventCreateWithFlags(&evW, cudaEventDisableTiming);

    cudaEventRecord(evF, 0);
    cudaStreamWaitEvent(side, evF, 0);

    {
        dim3 bb(16, 16);
        // side: wqkv transpose first (qkv GEMM gate), then the rest
        transpose_round_kernel<0><<<dim3(QKVD / 64, HIDD / 64), bb, 0, side>>>(
            wqkv, (__half*)wqkvT, HIDD, QKVD);
        cudaEventRecord(evQ, side);
        transpose_round_kernel<0><<<dim3(HIDD / 64, HIDD / 64), bb, 0, side>>>(
            wo, (__half*)woT, HIDD, HIDD);
        transpose_round_kernel<1><<<dim3(2 * INTD / 64, HIDD / 64), bb, 0, side>>>(
            wgu, (__half*)wguT, HIDD, 2 * INTD);
        transpose_round_kernel<0><<<dim3(HIDD / 64, INTD / 64), bb, 0, side>>>(
            wdn, (__half*)wdnT, INTD, HIDD);
        cudaEventRecord(evW, side);
    }

    // main: rmsnorm1 overlaps with wqkv transpose
    rmsnorm_kernel<<<NTOK, 256>>>(x, ln1, (__half*)xn);
    cudaStreamWaitEvent(0, evQ, 0);
    // 2. qkv = h @ wqkv  (fp16 out)  — overlaps with wo/wgu/wdn transposes
    tc_gemm<3><<<dim3(NTOK / TM, QKVD / TN), 256, GEMM_SMEM_TC>>>(
        (const __half*)xn, (const __half*)wqkvT, nullptr, qkvh, QKVD, HIDD);
    // 3. RoPE (in-place fp16)
    rope_kernel<<<NTOK, 256>>>((__half*)qkvh, pos);
    // 4. attention (fp16 mma, fp16 out)
    {
        dim3 g(SQ / 128, NH, BATCH);
        attn_mma_kernel<<<g, 256, ATTN_SMEM>>>((const __half*)qkvh, (__half*)attn);
    }
    cudaStreamWaitEvent(0, evW, 0);
    // 5. h1 = x + attn @ wo  (fp32 out)
    tc_gemm<1><<<dim3(NTOK / TM, HIDD / TN), 256, GEMM_SMEM_TC>>>(
        (const __half*)attn, (const __half*)woT, x, h1, HIDD, HIDD);
    // 6. h2 = rmsnorm(h1, ln2)  (fp16)
    rmsnorm_kernel<<<NTOK, 256>>>((const float*)h1, ln2, (__half*)h2);
    // 7+8. act = silu(h2 @ w_gate) * (h2 @ w_up)  (fp16, fused epilogue)
    tc_gemm<2><<<dim3(NTOK / TM, 2 * INTD / TN), 256, GEMM_SMEM_TC>>>(
        (const __half*)h2, (const __half*)wguT, nullptr, act, 2 * INTD, HIDD);
    // 9. out = h1 + act @ w_down  (fp32 out)
    tc_gemm<1><<<dim3(NTOK / TM, HIDD / TN), 256, GEMM_SMEM_TC>>>(
        (const __half*)act, (const __half*)wdnT, (const float*)h1, out, HIDD, INTD);
    // Streams/events intentionally not destroyed: kernel_launch is invoked only a
    // couple of times (correctness + capture); destroying capture-referenced
    // objects mid-capture is riskier than the tiny leak.
}